// round 11
// baseline (speedup 1.0000x reference)
#include <cuda_runtime.h>
#include <cuda_bf16.h>
#include <math.h>
#include <stdint.h>

// Problem constants
#define BB   8
#define HH   64
#define WW   64
#define NN   4096
#define CC   384
#define NH   8
#define DD   48
#define CHID 1536
#define BN   (BB*NN)
#define BNC  (BN*CC)
#define K1   (3*CC)        // 1152: logical split-K for C-contractions
#define K2   (3*CHID)      // 4608: logical split-K for fc2
#define A1   (2*CC)        // 768:  physical activation width (hi|lo)
#define A2   (2*CHID)      // 3072
#define LSPLIT 8
#define PERSIST_CTAS 296   // 2 CTAs x 148 SMs

// ---------------- scratch ----------------------------------------------------
__device__ float          g_xnF[BNC];
__device__ __nv_bfloat16  g_xnS[(size_t)BN*A1];
__device__ __nv_bfloat16  g_snS[(size_t)BN*A1];
__device__ float          g_kvF[(size_t)BN*2*CC];
__device__ float          g_attnP[(size_t)LSPLIT*BB*NH*DD*DD];
__device__ float          g_attn[BB*NH*DD*DD];
__device__ float          g_weff[BB*CC*CC];
__device__ float          g_w2F[BB*CC*CC];
__device__ __nv_bfloat16  g_w2T[(size_t)BB*CC*K1];
__device__ __nv_bfloat16  g_kvwT[(size_t)2*CC*K1];
__device__ __nv_bfloat16  g_f1wT[(size_t)CHID*K1];
__device__ __nv_bfloat16  g_f2wT[(size_t)CC*K2];
__device__ float          g_x2F[BNC];
__device__ float          g_x3F[BNC];
__device__ __nv_bfloat16  g_ln2S[(size_t)BN*A1];
__device__ __nv_bfloat16  g_h1S[(size_t)BN*A2];

// ---------------- PTX helpers ------------------------------------------------
__device__ __forceinline__ uint32_t smem_to_u32(const void* p) {
    uint32_t a;
    asm("{ .reg .u64 t; cvta.to.shared.u64 t, %1; cvt.u32.u64 %0, t; }" : "=r"(a) : "l"(p));
    return a;
}
__device__ __forceinline__ void cpasync16(uint32_t sa, const void* g) {
    asm volatile("cp.async.cg.shared.global [%0], [%1], 16;" :: "r"(sa), "l"(g));
}
#define CP_COMMIT() asm volatile("cp.async.commit_group;" ::: "memory")
#define CP_WAIT(n)  asm volatile("cp.async.wait_group %0;" :: "n"(n) : "memory")

__device__ __forceinline__ void ldsm4(uint32_t* r, uint32_t addr) {
    asm volatile("ldmatrix.sync.aligned.m8n8.x4.shared.b16 {%0,%1,%2,%3}, [%4];"
        : "=r"(r[0]), "=r"(r[1]), "=r"(r[2]), "=r"(r[3]) : "r"(addr));
}
__device__ __forceinline__ void hmma(float* c, const uint32_t* a, uint32_t b0, uint32_t b1) {
    asm volatile("mma.sync.aligned.m16n8k16.row.col.f32.bf16.bf16.f32 "
        "{%0,%1,%2,%3}, {%4,%5,%6,%7}, {%8,%9}, {%0,%1,%2,%3};"
        : "+f"(c[0]), "+f"(c[1]), "+f"(c[2]), "+f"(c[3])
        : "r"(a[0]), "r"(a[1]), "r"(a[2]), "r"(a[3]), "r"(b0), "r"(b1));
}

__device__ __forceinline__ void split2(float v, __nv_bfloat16& h, __nv_bfloat16& l) {
    h = __float2bfloat16(v);
    l = __float2bfloat16(v - __bfloat162float(h));
}

// ---------------- utility kernels -------------------------------------------
__device__ __forceinline__ float warpRed(float v) {
#pragma unroll
    for (int o = 16; o; o >>= 1) v += __shfl_xor_sync(0xffffffffu, v, o);
    return v;
}

// fused depthwise-3x3 CPE + LayerNorm over 4 tokens per block (spatial reuse).
__global__ void cpe_ln_kernel(const float* __restrict__ in, const float* __restrict__ w,
                              const float* __restrict__ cb, const float* __restrict__ gg,
                              const float* __restrict__ bb, float* __restrict__ raw,
                              float* __restrict__ outn, __nv_bfloat16* __restrict__ sp)
{
    int blk = blockIdx.x;                    // BN/4 blocks
    int b = blk >> 10;
    int n4 = blk & 1023;
    int y = n4 >> 4;
    int x0 = (n4 & 15) << 2;
    const float* inb = in + (size_t)b * NN * CC;

    float vals[3][4];
#pragma unroll
    for (int i = 0; i < 3; i++) {
        int c = threadIdx.x + i * 128;
        float wv[9];
#pragma unroll
        for (int j = 0; j < 9; j++) wv[j] = w[c * 9 + j];
        float bias0 = cb[c];
        float acc[4] = {bias0, bias0, bias0, bias0};
        float res[4];
#pragma unroll
        for (int dy = -1; dy <= 1; dy++) {
            int yy = y + dy;
            if ((unsigned)yy >= HH) continue;
            float v[6];
#pragma unroll
            for (int j = 0; j < 6; j++) {
                int xc = x0 - 1 + j;
                v[j] = ((unsigned)xc < WW) ? inb[((size_t)yy * WW + xc) * CC + c] : 0.f;
            }
            int wb = (dy + 1) * 3;
#pragma unroll
            for (int t = 0; t < 4; t++)
                acc[t] += v[t] * wv[wb] + v[t + 1] * wv[wb + 1] + v[t + 2] * wv[wb + 2];
            if (dy == 0) {
#pragma unroll
                for (int t = 0; t < 4; t++) res[t] = v[t + 1];
            }
        }
#pragma unroll
        for (int t = 0; t < 4; t++) vals[i][t] = acc[t] + res[t];
    }

    float s[4], q[4];
#pragma unroll
    for (int t = 0; t < 4; t++) {
        s[t] = vals[0][t] + vals[1][t] + vals[2][t];
        q[t] = vals[0][t] * vals[0][t] + vals[1][t] * vals[1][t] + vals[2][t] * vals[2][t];
        s[t] = warpRed(s[t]);
        q[t] = warpRed(q[t]);
    }
    __shared__ float rs[4][4], rq[4][4];
    int lane = threadIdx.x & 31, wp = threadIdx.x >> 5;
    if (!lane) {
#pragma unroll
        for (int t = 0; t < 4; t++) { rs[wp][t] = s[t]; rq[wp][t] = q[t]; }
    }
    __syncthreads();
    float mu[4], inv[4];
#pragma unroll
    for (int t = 0; t < 4; t++) {
        float tot = rs[0][t] + rs[1][t] + rs[2][t] + rs[3][t];
        float tq  = rq[0][t] + rq[1][t] + rq[2][t] + rq[3][t];
        mu[t] = tot * (1.f / CC);
        float var = tq * (1.f / CC) - mu[t] * mu[t];
        inv[t] = rsqrtf(var + 1e-5f);
    }

    size_t tokBase = (size_t)b * NN + (size_t)y * WW + x0;
#pragma unroll
    for (int i = 0; i < 3; i++) {
        int c = threadIdx.x + i * 128;
        float g = gg[c], be = bb[c];
#pragma unroll
        for (int t = 0; t < 4; t++) {
            size_t tok = tokBase + t;
            if (raw) raw[tok * CC + c] = vals[i][t];
            float v = (vals[i][t] - mu[t]) * inv[t] * g + be;
            if (outn) outn[tok * CC + c] = v;
            if (sp) {
                __nv_bfloat16 h, l;
                split2(v, h, l);
                sp[tok * A1 + c] = h;
                sp[tok * A1 + CC + c] = l;
            }
        }
    }
}

// logits partials: P[s][b,h,d,e] = sum_{n in slice s} k[n,d]*v[n,e]  (no atomics)
__global__ void logits_kernel(const float* __restrict__ kv, float* __restrict__ part)
{
    int bh = blockIdx.x;
    int b = bh >> 3, h = bh & 7;
    const float* kb = kv + (size_t)b * NN * (2 * CC) + h * DD;
    const float* vb = kb + CC;
    __shared__ float ks[32][DD], vs[32][DD];
    int d0 = (threadIdx.x >> 4) * 3, e0 = (threadIdx.x & 15) * 3;
    float acc[3][3] = {};
    int n0 = blockIdx.y * (NN / LSPLIT);
    for (int nc = 0; nc < NN / LSPLIT; nc += 32) {
        for (int idx = threadIdx.x; idx < 32 * DD; idx += 256) {
            int r = idx / DD, c = idx % DD;
            size_t off = (size_t)(n0 + nc + r) * (2 * CC) + c;
            ks[r][c] = kb[off];
            vs[r][c] = vb[off];
        }
        __syncthreads();
#pragma unroll 8
        for (int r = 0; r < 32; r++) {
            float k0 = ks[r][d0], k1 = ks[r][d0 + 1], k2 = ks[r][d0 + 2];
            float v0 = vs[r][e0], v1 = vs[r][e0 + 1], v2 = vs[r][e0 + 2];
            acc[0][0] += k0 * v0; acc[0][1] += k0 * v1; acc[0][2] += k0 * v2;
            acc[1][0] += k1 * v0; acc[1][1] += k1 * v1; acc[1][2] += k1 * v2;
            acc[2][0] += k2 * v0; acc[2][1] += k2 * v1; acc[2][2] += k2 * v2;
        }
        __syncthreads();
    }
    float* P = part + ((size_t)blockIdx.y * BB * NH + bh) * DD * DD;
#pragma unroll
    for (int i = 0; i < 3; i++)
#pragma unroll
        for (int j = 0; j < 3; j++)
            P[(d0 + i) * DD + (e0 + j)] = acc[i][j];
}

// reduce partials + softmax over last dim (48), scale = d^-0.5
__global__ void softmax_kernel(const float* __restrict__ part, float* __restrict__ attn)
{
    int bh = blockIdx.x;
    size_t rowOff = (size_t)bh * DD * DD + threadIdx.x * DD;
    const float scale = 0.14433756729740643f;
    float r[DD];
#pragma unroll
    for (int e = 0; e < DD; e++) r[e] = 0.f;
    for (int s = 0; s < LSPLIT; s++) {
        const float* P = part + (size_t)s * BB * NH * DD * DD + rowOff;
#pragma unroll
        for (int e = 0; e < DD; e++) r[e] += P[e];
    }
    float mx = -1e30f;
#pragma unroll
    for (int e = 0; e < DD; e++) { r[e] *= scale; mx = fmaxf(mx, r[e]); }
    float s = 0.f;
#pragma unroll
    for (int e = 0; e < DD; e++) { r[e] = expf(r[e] - mx); s += r[e]; }
    float inv = 1.f / s;
    float* L = attn + rowOff;
#pragma unroll
    for (int e = 0; e < DD; e++) L[e] = r[e] * inv;
}

__global__ void weff_kernel(const float* __restrict__ attn, const float* __restrict__ pw,
                            float* __restrict__ weff)
{
    int b = blockIdx.x >> 3, h = blockIdx.x & 7;
    __shared__ float as[DD][DD];
    __shared__ float ps[DD][64];
    const float* A = attn + (size_t)blockIdx.x * DD * DD;
    for (int idx = threadIdx.x; idx < DD * DD; idx += 256) as[idx / DD][idx % DD] = A[idx];
    int jj = threadIdx.x & 63;
    int e0 = (threadIdx.x >> 6) * 12;
    for (int j0 = 0; j0 < CC; j0 += 64) {
        __syncthreads();
        for (int idx = threadIdx.x; idx < DD * 64; idx += 256) {
            int d = idx >> 6, j = idx & 63;
            ps[d][j] = pw[(size_t)(h * DD + d) * CC + j0 + j];
        }
        __syncthreads();
        for (int ei = 0; ei < 12; ei++) {
            int e = e0 + ei;
            float acc = 0.f;
#pragma unroll
            for (int d = 0; d < DD; d++) acc += as[d][e] * ps[d][jj];
            weff[((size_t)b * CC + h * DD + e) * CC + j0 + jj] = acc;
        }
    }
}

// split + transpose: W fp32 [K,N] -> T bf16 [N,3K] blocks (hi, hi, lo); batched over z
__global__ void splitT_kernel(const float* __restrict__ W, __nv_bfloat16* __restrict__ T,
                              int K, int N, long long wStride, long long tStride)
{
    __shared__ float ts[32][33];
    const float* Wz = W + (long long)blockIdx.z * wStride;
    __nv_bfloat16* Tz = T + (long long)blockIdx.z * tStride;
    int k0 = blockIdx.y * 32, n0 = blockIdx.x * 32;
    int tx = threadIdx.x, ty = threadIdx.y;   // 32 x 8
#pragma unroll
    for (int i = 0; i < 32; i += 8)
        ts[ty + i][tx] = Wz[(size_t)(k0 + ty + i) * N + n0 + tx];
    __syncthreads();
#pragma unroll
    for (int i = 0; i < 32; i += 8) {
        int n = n0 + ty + i, k = k0 + tx;
        float v = ts[tx][ty + i];
        __nv_bfloat16 h, l;
        split2(v, h, l);
        size_t base = (size_t)n * 3 * K;
        Tz[base + k] = h;
        Tz[base + K + k] = h;
        Tz[base + 2 * K + k] = l;
    }
}

// ---------------- fp32 SIMT GEMM (small per-batch fold, batched over z) ------
#define GBM 128
#define GBN 128
#define GBK 16
__global__ __launch_bounds__(256, 2)
void gemm_f32(const float* __restrict__ A, const float* __restrict__ Bm,
              float* __restrict__ Cd, int M, int Nn, int K,
              long long bStride, long long cStride)
{
    __shared__ float As[2][GBK][GBM + 4];
    __shared__ float Bs[2][GBK][GBN];
    int tid = threadIdx.x;
    int rowStart = blockIdx.y * GBM;
    int colStart = blockIdx.x * GBN;
    const float* Bz = Bm + (long long)blockIdx.z * bStride;
    float* Cz = Cd + (long long)blockIdx.z * cStride;

    float4 aP[2], bP[2];
    auto gload = [&](int kt) {
#pragma unroll
        for (int i = 0; i < 2; i++) {
            int idx = tid + i * 256;
            int r = idx >> 2, k4 = (idx & 3) << 2;
            aP[i] = *reinterpret_cast<const float4*>(A + (size_t)(rowStart + r) * K + kt * GBK + k4);
        }
#pragma unroll
        for (int i = 0; i < 2; i++) {
            int idx = tid + i * 256;
            int r = idx >> 5, c = (idx & 31) << 2;
            bP[i] = *reinterpret_cast<const float4*>(Bz + (size_t)(kt * GBK + r) * Nn + colStart + c);
        }
    };
    auto sstore = [&](int buf) {
#pragma unroll
        for (int i = 0; i < 2; i++) {
            int idx = tid + i * 256;
            int r = idx >> 2, k4 = (idx & 3) << 2;
            As[buf][k4 + 0][r] = aP[i].x;
            As[buf][k4 + 1][r] = aP[i].y;
            As[buf][k4 + 2][r] = aP[i].z;
            As[buf][k4 + 3][r] = aP[i].w;
        }
#pragma unroll
        for (int i = 0; i < 2; i++) {
            int idx = tid + i * 256;
            int r = idx >> 5, c = (idx & 31) << 2;
            *reinterpret_cast<float4*>(&Bs[buf][r][c]) = bP[i];
        }
    };

    int tm = (tid >> 4) << 3;
    int tn = (tid & 15) << 3;
    float acc[8][8] = {};

    int nk = K / GBK;
    gload(0); sstore(0); __syncthreads();
    for (int kt = 0; kt < nk; kt++) {
        int buf = kt & 1;
        if (kt + 1 < nk) gload(kt + 1);
#pragma unroll
        for (int k = 0; k < GBK; k++) {
            float a[8], bfr[8];
            *(float4*)&a[0]   = *(const float4*)&As[buf][k][tm];
            *(float4*)&a[4]   = *(const float4*)&As[buf][k][tm + 4];
            *(float4*)&bfr[0] = *(const float4*)&Bs[buf][k][tn];
            *(float4*)&bfr[4] = *(const float4*)&Bs[buf][k][tn + 4];
#pragma unroll
            for (int i = 0; i < 8; i++)
#pragma unroll
                for (int j = 0; j < 8; j++)
                    acc[i][j] = fmaf(a[i], bfr[j], acc[i][j]);
        }
        if (kt + 1 < nk) sstore((kt + 1) & 1);
        __syncthreads();
    }
#pragma unroll
    for (int i = 0; i < 8; i++) {
        size_t ro = (size_t)(rowStart + tm + i) * Nn + colStart + tn;
        *(float4*)(Cz + ro)     = *(float4*)&acc[i][0];
        *(float4*)(Cz + ro + 4) = *(float4*)&acc[i][4];
    }
}

// ---------------- HMMA bf16-split GEMM (persistent CTAs) ---------------------
// C[m,n] = sum_k A[m,ka(k)]*B[n,k], logical K = Kp = 3*Kc.
// A physical width 2*Kc (hi|lo); k-block remap: ka = k < 2Kc ? k : k-2Kc.
// B physical width Kp (hi|hi|lo). CTA tile 128x128x64, 128 threads (4 warps x 64x64).
// PERSISTENT: gridDim.x = 296; each CTA loops over output tiles -> no wave tail.
// Mainloop: R8-proven two-barrier 3-stage cp.async pipeline.
// MODE 0: fp32 C; MODE 1: C = acc+bias+res; MODE 2: gelu(acc+bias) split [hi|lo]->Csplit.
#define MM_STAGES 3
#define MM_STAGE_B 32768            // A 16KB + B 16KB
#define MM_SMEM (MM_STAGES*MM_STAGE_B)

__device__ __forceinline__ void mm_load(uint32_t buf, const __nv_bfloat16* aSrc, int aStride,
                                        const __nv_bfloat16* bSrc, int bStride, int tid)
{
#pragma unroll
    for (int i = 0; i < 8; i++) {
        int idx = tid + i * 128;
        int row = idx >> 3, c = idx & 7;
        uint32_t so = (uint32_t)(row * 128 + ((c ^ (row & 7)) << 4));
        cpasync16(buf + so, aSrc + (size_t)row * aStride + c * 8);
        cpasync16(buf + 16384 + so, bSrc + (size_t)row * bStride + c * 8);
    }
}

template<int MODE>
__global__ __launch_bounds__(128, 2)
void gemm_mma(const __nv_bfloat16* __restrict__ A, const __nv_bfloat16* __restrict__ B,
              const float* __restrict__ bias, const float* __restrict__ res,
              float* __restrict__ C, __nv_bfloat16* __restrict__ Csplit,
              int Nn, int Kp, int nOut, long long bBatchStride,
              int nTilesX, int nTiles)
{
    extern __shared__ char smem[];
    uint32_t sb = smem_to_u32(smem);
    int tid = threadIdx.x;
    int wid = tid >> 5, lane = tid & 31;
    int wm = wid & 1, wn = wid >> 1;          // warp grid 2x2, tile 64x64

    int Kc = Kp / 3;
    int AS = 2 * Kc;
    int NTk = Kp / 64;

    int aRow[4], bRow[4];
#pragma unroll
    for (int mt = 0; mt < 4; mt++) aRow[mt] = wm * 64 + mt * 16 + (lane & 15);
    int aHi = (lane >> 4) & 1;
#pragma unroll
    for (int p = 0; p < 4; p++) bRow[p] = wn * 64 + p * 16 + (lane & 7) + ((lane & 16) ? 8 : 0);
    int bHi = (lane >> 3) & 1;

    for (int t = blockIdx.x; t < nTiles; t += gridDim.x) {
        int rowStart = (t / nTilesX) * 128;
        int colStart = (t % nTilesX) * 128;
        const __nv_bfloat16* Ab = A + (size_t)rowStart * AS;
        const __nv_bfloat16* Bb = B + (size_t)colStart * Kp;
        if (bBatchStride) Bb += (long long)(rowStart >> 12) * bBatchStride;

        float acc[4][8][4];
#pragma unroll
        for (int i = 0; i < 4; i++)
#pragma unroll
            for (int j = 0; j < 8; j++)
#pragma unroll
                for (int q = 0; q < 4; q++) acc[i][j][q] = 0.f;

        auto loadTile = [&](int kt) {
            int kk = kt * 64;
            int akk = (kk < AS) ? kk : kk - AS;   // remap third block back onto hi
            mm_load(sb + (kt % MM_STAGES) * MM_STAGE_B, Ab + akk, AS, Bb + kk, Kp, tid);
            CP_COMMIT();
        };

        loadTile(0);
        loadTile(1);

        for (int kt = 0; kt < NTk; kt++) {
            if (kt + 2 < NTk) {
                loadTile(kt + 2);
                CP_WAIT(2);                        // tile kt complete (own groups)
            } else if (kt + 2 == NTk) {
                CP_WAIT(1);
            } else {
                CP_WAIT(0);
            }
            __syncthreads();                       // tile kt visible to all warps

            uint32_t aB = sb + (kt % MM_STAGES) * MM_STAGE_B;
            uint32_t bB = aB + 16384;
#pragma unroll
            for (int ks = 0; ks < 4; ks++) {
                uint32_t af[4][4], bf[4][4];
#pragma unroll
                for (int mt = 0; mt < 4; mt++) {
                    int r = aRow[mt];
                    ldsm4(af[mt], aB + r * 128 + (((2 * ks + aHi) ^ (r & 7)) << 4));
                }
#pragma unroll
                for (int p = 0; p < 4; p++) {
                    int r = bRow[p];
                    ldsm4(bf[p], bB + r * 128 + (((2 * ks + bHi) ^ (r & 7)) << 4));
                }
#pragma unroll
                for (int mt = 0; mt < 4; mt++)
#pragma unroll
                    for (int nt = 0; nt < 8; nt++)
                        hmma(acc[mt][nt], af[mt], bf[nt >> 1][(nt & 1) * 2], bf[nt >> 1][(nt & 1) * 2 + 1]);
            }
            __syncthreads();                       // readers done before next overwrite
        }

        // epilogue (register/global only; final barrier above isolates smem)
        int rBase = rowStart + wm * 64 + (lane >> 2);
        int cBase = colStart + wn * 64 + (lane & 3) * 2;
#pragma unroll
        for (int mt = 0; mt < 4; mt++) {
#pragma unroll
            for (int half = 0; half < 2; half++) {
                int r = rBase + mt * 16 + half * 8;
#pragma unroll
                for (int nt = 0; nt < 8; nt++) {
                    int col = cBase + nt * 8;
                    float v0 = acc[mt][nt][half * 2 + 0];
                    float v1 = acc[mt][nt][half * 2 + 1];
                    if (MODE == 0) {
                        float2 v = make_float2(v0, v1);
                        *(float2*)(C + (size_t)r * Nn + col) = v;
                    } else if (MODE == 1) {
                        size_t off = (size_t)r * Nn + col;
                        float2 rv = *(const float2*)(res + off);
                        float2 v = make_float2(v0 + bias[col] + rv.x, v1 + bias[col + 1] + rv.y);
                        *(float2*)(C + off) = v;
                    } else {
                        v0 += bias[col];
                        v1 += bias[col + 1];
                        v0 = 0.5f * v0 * (1.f + erff(v0 * 0.70710678118654752f));
                        v1 = 0.5f * v1 * (1.f + erff(v1 * 0.70710678118654752f));
                        __nv_bfloat16 h0, l0, h1, l1;
                        split2(v0, h0, l0);
                        split2(v1, h1, l1);
                        __nv_bfloat162 hh; hh.x = h0; hh.y = h1;
                        __nv_bfloat162 ll; ll.x = l0; ll.y = l1;
                        size_t mb = (size_t)r * 2 * nOut + col;
                        *(__nv_bfloat162*)(Csplit + mb)        = hh;   // hi
                        *(__nv_bfloat162*)(Csplit + mb + nOut) = ll;   // lo
                    }
                }
            }
        }
    }
}

// ---------------- launcher ---------------------------------------------------
extern "C" void kernel_launch(void* const* d_in, const int* in_sizes, int n_in,
                              void* d_out, int out_size)
{
    const float* x   = (const float*)d_in[0];
    const float* src = (const float*)d_in[1];
    const float* c0w = (const float*)d_in[4];
    const float* c0b = (const float*)d_in[5];
    const float* c1w = (const float*)d_in[6];
    const float* c1b = (const float*)d_in[7];
    const float* n1g = (const float*)d_in[8];
    const float* n1b = (const float*)d_in[9];
    const float* qw  = (const float*)d_in[10];
    const float* kvw = (const float*)d_in[11];
    const float* pw  = (const float*)d_in[12];
    const float* pb  = (const float*)d_in[13];
    const float* n2g = (const float*)d_in[14];
    const float* n2b = (const float*)d_in[15];
    const float* f1w = (const float*)d_in[16];
    const float* f1b = (const float*)d_in[17];
    const float* f2w = (const float*)d_in[18];
    const float* f2b = (const float*)d_in[19];
    float* out = (float*)d_out;

    float *xnF, *kvF, *attnP, *attn, *weff, *w2F, *x2F, *x3F;
    __nv_bfloat16 *xnS, *snS, *w2T, *kvwT, *f1wT, *f2wT, *ln2S, *h1S;
    cudaGetSymbolAddress((void**)&xnF, g_xnF);
    cudaGetSymbolAddress((void**)&xnS, g_xnS);
    cudaGetSymbolAddress((void**)&snS, g_snS);
    cudaGetSymbolAddress((void**)&kvF, g_kvF);
    cudaGetSymbolAddress((void**)&attnP, g_attnP);
    cudaGetSymbolAddress((void**)&attn, g_attn);
    cudaGetSymbolAddress((void**)&weff, g_weff);
    cudaGetSymbolAddress((void**)&w2F, g_w2F);
    cudaGetSymbolAddress((void**)&w2T, g_w2T);
    cudaGetSymbolAddress((void**)&kvwT, g_kvwT);
    cudaGetSymbolAddress((void**)&f1wT, g_f1wT);
    cudaGetSymbolAddress((void**)&f2wT, g_f2wT);
    cudaGetSymbolAddress((void**)&x2F, g_x2F);
    cudaGetSymbolAddress((void**)&x3F, g_x3F);
    cudaGetSymbolAddress((void**)&ln2S, g_ln2S);
    cudaGetSymbolAddress((void**)&h1S, g_h1S);

    cudaFuncSetAttribute(gemm_mma<0>, cudaFuncAttributeMaxDynamicSharedMemorySize, MM_SMEM);
    cudaFuncSetAttribute(gemm_mma<1>, cudaFuncAttributeMaxDynamicSharedMemorySize, MM_SMEM);
    cudaFuncSetAttribute(gemm_mma<2>, cudaFuncAttributeMaxDynamicSharedMemorySize, MM_SMEM);

    dim3 tb(32, 8);

    // idx 0: cpe0 + LN1 on source (produces snS for kv gemm)
    cpe_ln_kernel<<<BN / 4, 128>>>(src, c0w, c0b, n1g, n1b, nullptr, nullptr, snS);
    // idx 1: kv weight split
    splitT_kernel<<<dim3(2 * CC / 32, CC / 32), tb>>>(kvw, kvwT, CC, 2 * CC, 0, 0);
    // idx 2: cpe0 + LN1 on x
    cpe_ln_kernel<<<BN / 4, 128>>>(x, c0w, c0b, n1g, n1b, nullptr, xnF, xnS);
    // idx 3 (ncu capture target): kv = sn @ kv_w  (persistent)
    gemm_mma<0><<<PERSIST_CTAS, 128, MM_SMEM>>>(
        snS, kvwT, nullptr, nullptr, kvF, nullptr, 2 * CC, K1, 0, 0,
        2 * CC / 128, (2 * CC / 128) * (BN / 128));
    // idx 4: logits partials (atomic-free)
    logits_kernel<<<dim3(BB * NH, LSPLIT), 256>>>(kvF, attnP);
    // idx 5: reduce + softmax
    softmax_kernel<<<BB * NH, DD>>>(attnP, attn);
    // weight transposes for MLP
    splitT_kernel<<<dim3(CHID / 32, CC / 32), tb>>>(f1w, f1wT, CC, CHID, 0, 0);
    splitT_kernel<<<dim3(CC / 32, CHID / 32), tb>>>(f2w, f2wT, CHID, CC, 0, 0);

    // fold attn into proj_w, then q_w: W2[b] = q_w @ weff[b]
    weff_kernel<<<BB * NH, 256>>>(attn, pw, weff);
    gemm_f32<<<dim3(CC / GBN, CC / GBM, BB), 256>>>(
        qw, weff, w2F, CC, CC, CC, (long long)CC * CC, (long long)CC * CC);
    splitT_kernel<<<dim3(CC / 32, CC / 32, BB), tb>>>(
        w2F, w2T, CC, CC, (long long)CC * CC, (long long)CC * K1);

    // x2 = xn @ W2[b] + proj_b + xn  (persistent)
    gemm_mma<1><<<PERSIST_CTAS, 128, MM_SMEM>>>(
        xnS, w2T, pb, xnF, x2F, nullptr, CC, K1, 0, (long long)CC * K1,
        CC / 128, (CC / 128) * (BN / 128));

    // cpe1 + LN2
    cpe_ln_kernel<<<BN / 4, 128>>>(x2F, c1w, c1b, n2g, n2b, x3F, nullptr, ln2S);

    // h1 = gelu(ln2 @ fc1_w + fc1_b)   (split-bf16 out, [hi|lo]) (persistent)
    gemm_mma<2><<<PERSIST_CTAS, 128, MM_SMEM>>>(
        ln2S, f1wT, f1b, nullptr, nullptr, h1S, CHID, K1, CHID, 0,
        CHID / 128, (CHID / 128) * (BN / 128));

    // out = h1 @ fc2_w + fc2_b + x3  (persistent)
    gemm_mma<1><<<PERSIST_CTAS, 128, MM_SMEM>>>(
        h1S, f2wT, f2b, x3F, out, nullptr, CC, K2, 0, 0,
        CC / 128, (CC / 128) * (BN / 128));
}

// round 12
// speedup vs baseline: 1.0562x; 1.0562x over previous
#include <cuda_runtime.h>
#include <cuda_bf16.h>
#include <math.h>
#include <stdint.h>

// Problem constants
#define BB   8
#define HH   64
#define WW   64
#define NN   4096
#define CC   384
#define NH   8
#define DD   48
#define CHID 1536
#define BN   (BB*NN)
#define BNC  (BN*CC)
#define K1   (3*CC)        // 1152: logical split-K for C-contractions
#define K2   (3*CHID)      // 4608: logical split-K for fc2
#define A1   (2*CC)        // 768:  physical activation width (hi|lo)
#define A2   (2*CHID)      // 3072
#define LSPLIT 8

// ---------------- scratch ----------------------------------------------------
__device__ __nv_bfloat16  g_xnS[(size_t)BN*A1];
__device__ __nv_bfloat16  g_snS[(size_t)BN*A1];
__device__ float          g_kvF[(size_t)BN*2*CC];
__device__ float          g_attnP[(size_t)LSPLIT*BB*NH*DD*DD];
__device__ float          g_attn[BB*NH*DD*DD];
__device__ float          g_weff[BB*CC*CC];
__device__ float          g_w2F[BB*CC*CC];
__device__ __nv_bfloat16  g_w2T[(size_t)BB*CC*K1];
__device__ __nv_bfloat16  g_kvwT[(size_t)2*CC*K1];
__device__ __nv_bfloat16  g_f1wT[(size_t)CHID*K1];
__device__ __nv_bfloat16  g_f2wT[(size_t)CC*K2];
__device__ float          g_x2F[BNC];
__device__ float          g_x3F[BNC];
__device__ __nv_bfloat16  g_ln2S[(size_t)BN*A1];
__device__ __nv_bfloat16  g_h1S[(size_t)BN*A2];

// ---------------- PTX helpers ------------------------------------------------
__device__ __forceinline__ uint32_t smem_to_u32(const void* p) {
    uint32_t a;
    asm("{ .reg .u64 t; cvta.to.shared.u64 t, %1; cvt.u32.u64 %0, t; }" : "=r"(a) : "l"(p));
    return a;
}
__device__ __forceinline__ void cpasync16(uint32_t sa, const void* g) {
    asm volatile("cp.async.cg.shared.global [%0], [%1], 16;" :: "r"(sa), "l"(g));
}
#define CP_COMMIT() asm volatile("cp.async.commit_group;" ::: "memory")
#define CP_WAIT(n)  asm volatile("cp.async.wait_group %0;" :: "n"(n) : "memory")

__device__ __forceinline__ void ldsm4(uint32_t* r, uint32_t addr) {
    asm volatile("ldmatrix.sync.aligned.m8n8.x4.shared.b16 {%0,%1,%2,%3}, [%4];"
        : "=r"(r[0]), "=r"(r[1]), "=r"(r[2]), "=r"(r[3]) : "r"(addr));
}
__device__ __forceinline__ void hmma(float* c, const uint32_t* a, uint32_t b0, uint32_t b1) {
    asm volatile("mma.sync.aligned.m16n8k16.row.col.f32.bf16.bf16.f32 "
        "{%0,%1,%2,%3}, {%4,%5,%6,%7}, {%8,%9}, {%0,%1,%2,%3};"
        : "+f"(c[0]), "+f"(c[1]), "+f"(c[2]), "+f"(c[3])
        : "r"(a[0]), "r"(a[1]), "r"(a[2]), "r"(a[3]), "r"(b0), "r"(b1));
}

__device__ __forceinline__ void split2(float v, __nv_bfloat16& h, __nv_bfloat16& l) {
    h = __float2bfloat16(v);
    l = __float2bfloat16(v - __bfloat162float(h));
}

// ---------------- utility kernels -------------------------------------------
__device__ __forceinline__ float warpRed(float v) {
#pragma unroll
    for (int o = 16; o; o >>= 1) v += __shfl_xor_sync(0xffffffffu, v, o);
    return v;
}

// core of cpe+ln over 4 tokens; writes optional fp32 raw + split-bf16 out
__device__ __forceinline__ void cpe_ln_body(
    const float* __restrict__ in, const float* __restrict__ w,
    const float* __restrict__ cb, const float* __restrict__ gg,
    const float* __restrict__ bb, float* __restrict__ raw,
    __nv_bfloat16* __restrict__ sp, int blk)
{
    int b = blk >> 10;
    int n4 = blk & 1023;
    int y = n4 >> 4;
    int x0 = (n4 & 15) << 2;
    const float* inb = in + (size_t)b * NN * CC;

    float vals[3][4];
#pragma unroll
    for (int i = 0; i < 3; i++) {
        int c = threadIdx.x + i * 128;
        float wv[9];
#pragma unroll
        for (int j = 0; j < 9; j++) wv[j] = w[c * 9 + j];
        float bias0 = cb[c];
        float acc[4] = {bias0, bias0, bias0, bias0};
        float res[4];
#pragma unroll
        for (int dy = -1; dy <= 1; dy++) {
            int yy = y + dy;
            if ((unsigned)yy >= HH) continue;
            float v[6];
#pragma unroll
            for (int j = 0; j < 6; j++) {
                int xc = x0 - 1 + j;
                v[j] = ((unsigned)xc < WW) ? inb[((size_t)yy * WW + xc) * CC + c] : 0.f;
            }
            int wb = (dy + 1) * 3;
#pragma unroll
            for (int t = 0; t < 4; t++)
                acc[t] += v[t] * wv[wb] + v[t + 1] * wv[wb + 1] + v[t + 2] * wv[wb + 2];
            if (dy == 0) {
#pragma unroll
                for (int t = 0; t < 4; t++) res[t] = v[t + 1];
            }
        }
#pragma unroll
        for (int t = 0; t < 4; t++) vals[i][t] = acc[t] + res[t];
    }

    float s[4], q[4];
#pragma unroll
    for (int t = 0; t < 4; t++) {
        s[t] = vals[0][t] + vals[1][t] + vals[2][t];
        q[t] = vals[0][t] * vals[0][t] + vals[1][t] * vals[1][t] + vals[2][t] * vals[2][t];
        s[t] = warpRed(s[t]);
        q[t] = warpRed(q[t]);
    }
    __shared__ float rs[4][4], rq[4][4];
    int lane = threadIdx.x & 31, wp = threadIdx.x >> 5;
    if (!lane) {
#pragma unroll
        for (int t = 0; t < 4; t++) { rs[wp][t] = s[t]; rq[wp][t] = q[t]; }
    }
    __syncthreads();
    float mu[4], inv[4];
#pragma unroll
    for (int t = 0; t < 4; t++) {
        float tot = rs[0][t] + rs[1][t] + rs[2][t] + rs[3][t];
        float tq  = rq[0][t] + rq[1][t] + rq[2][t] + rq[3][t];
        mu[t] = tot * (1.f / CC);
        float var = tq * (1.f / CC) - mu[t] * mu[t];
        inv[t] = rsqrtf(var + 1e-5f);
    }

    size_t tokBase = (size_t)b * NN + (size_t)y * WW + x0;
#pragma unroll
    for (int i = 0; i < 3; i++) {
        int c = threadIdx.x + i * 128;
        float g = gg[c], be = bb[c];
#pragma unroll
        for (int t = 0; t < 4; t++) {
            size_t tok = tokBase + t;
            if (raw) raw[tok * CC + c] = vals[i][t];
            float v = (vals[i][t] - mu[t]) * inv[t] * g + be;
            __nv_bfloat16 h, l;
            split2(v, h, l);
            sp[tok * A1 + c] = h;
            sp[tok * A1 + CC + c] = l;
        }
    }
}

// dual cpe0+LN1: blockIdx.y = 0 -> x -> xnS ; 1 -> source -> snS (split out only)
__global__ void cpe_ln_dual_kernel(const float* __restrict__ x, const float* __restrict__ src,
                                   const float* __restrict__ w, const float* __restrict__ cb,
                                   const float* __restrict__ gg, const float* __restrict__ bb,
                                   __nv_bfloat16* __restrict__ xnS, __nv_bfloat16* __restrict__ snS)
{
    if (blockIdx.y == 0)
        cpe_ln_body(x, w, cb, gg, bb, nullptr, xnS, blockIdx.x);
    else
        cpe_ln_body(src, w, cb, gg, bb, nullptr, snS, blockIdx.x);
}

// single cpe+LN (used for cpe1+LN2: raw -> x3F, split -> ln2S)
__global__ void cpe_ln_kernel(const float* __restrict__ in, const float* __restrict__ w,
                              const float* __restrict__ cb, const float* __restrict__ gg,
                              const float* __restrict__ bb, float* __restrict__ raw,
                              __nv_bfloat16* __restrict__ sp)
{
    cpe_ln_body(in, w, cb, gg, bb, raw, sp, blockIdx.x);
}

// logits partials: P[s][b,h,d,e] = sum_{n in slice s} k[n,d]*v[n,e]  (no atomics)
__global__ void logits_kernel(const float* __restrict__ kv, float* __restrict__ part)
{
    int bh = blockIdx.x;
    int b = bh >> 3, h = bh & 7;
    const float* kb = kv + (size_t)b * NN * (2 * CC) + h * DD;
    const float* vb = kb + CC;
    __shared__ float ks[32][DD], vs[32][DD];
    int d0 = (threadIdx.x >> 4) * 3, e0 = (threadIdx.x & 15) * 3;
    float acc[3][3] = {};
    int n0 = blockIdx.y * (NN / LSPLIT);
    for (int nc = 0; nc < NN / LSPLIT; nc += 32) {
        for (int idx = threadIdx.x; idx < 32 * DD; idx += 256) {
            int r = idx / DD, c = idx % DD;
            size_t off = (size_t)(n0 + nc + r) * (2 * CC) + c;
            ks[r][c] = kb[off];
            vs[r][c] = vb[off];
        }
        __syncthreads();
#pragma unroll 8
        for (int r = 0; r < 32; r++) {
            float k0 = ks[r][d0], k1 = ks[r][d0 + 1], k2 = ks[r][d0 + 2];
            float v0 = vs[r][e0], v1 = vs[r][e0 + 1], v2 = vs[r][e0 + 2];
            acc[0][0] += k0 * v0; acc[0][1] += k0 * v1; acc[0][2] += k0 * v2;
            acc[1][0] += k1 * v0; acc[1][1] += k1 * v1; acc[1][2] += k1 * v2;
            acc[2][0] += k2 * v0; acc[2][1] += k2 * v1; acc[2][2] += k2 * v2;
        }
        __syncthreads();
    }
    float* P = part + ((size_t)blockIdx.y * BB * NH + bh) * DD * DD;
#pragma unroll
    for (int i = 0; i < 3; i++)
#pragma unroll
        for (int j = 0; j < 3; j++)
            P[(d0 + i) * DD + (e0 + j)] = acc[i][j];
}

// reduce partials + softmax over last dim (48), scale = d^-0.5
__global__ void softmax_kernel(const float* __restrict__ part, float* __restrict__ attn)
{
    int bh = blockIdx.x;
    size_t rowOff = (size_t)bh * DD * DD + threadIdx.x * DD;
    const float scale = 0.14433756729740643f;
    float r[DD];
#pragma unroll
    for (int e = 0; e < DD; e++) r[e] = 0.f;
    for (int s = 0; s < LSPLIT; s++) {
        const float* P = part + (size_t)s * BB * NH * DD * DD + rowOff;
#pragma unroll
        for (int e = 0; e < DD; e++) r[e] += P[e];
    }
    float mx = -1e30f;
#pragma unroll
    for (int e = 0; e < DD; e++) { r[e] *= scale; mx = fmaxf(mx, r[e]); }
    float s = 0.f;
#pragma unroll
    for (int e = 0; e < DD; e++) { r[e] = expf(r[e] - mx); s += r[e]; }
    float inv = 1.f / s;
    float* L = attn + rowOff;
#pragma unroll
    for (int e = 0; e < DD; e++) L[e] = r[e] * inv;
}

__global__ void weff_kernel(const float* __restrict__ attn, const float* __restrict__ pw,
                            float* __restrict__ weff)
{
    int b = blockIdx.x >> 3, h = blockIdx.x & 7;
    __shared__ float as[DD][DD];
    __shared__ float ps[DD][64];
    const float* A = attn + (size_t)blockIdx.x * DD * DD;
    for (int idx = threadIdx.x; idx < DD * DD; idx += 256) as[idx / DD][idx % DD] = A[idx];
    int jj = threadIdx.x & 63;
    int e0 = (threadIdx.x >> 6) * 12;
    for (int j0 = 0; j0 < CC; j0 += 64) {
        __syncthreads();
        for (int idx = threadIdx.x; idx < DD * 64; idx += 256) {
            int d = idx >> 6, j = idx & 63;
            ps[d][j] = pw[(size_t)(h * DD + d) * CC + j0 + j];
        }
        __syncthreads();
        for (int ei = 0; ei < 12; ei++) {
            int e = e0 + ei;
            float acc = 0.f;
#pragma unroll
            for (int d = 0; d < DD; d++) acc += as[d][e] * ps[d][jj];
            weff[((size_t)b * CC + h * DD + e) * CC + j0 + jj] = acc;
        }
    }
}

// split + transpose: W fp32 [K,N] -> T bf16 [N,3K] blocks (hi, hi, lo); batched over z
__global__ void splitT_kernel(const float* __restrict__ W, __nv_bfloat16* __restrict__ T,
                              int K, int N, long long wStride, long long tStride)
{
    __shared__ float ts[32][33];
    const float* Wz = W + (long long)blockIdx.z * wStride;
    __nv_bfloat16* Tz = T + (long long)blockIdx.z * tStride;
    int k0 = blockIdx.y * 32, n0 = blockIdx.x * 32;
    int tx = threadIdx.x, ty = threadIdx.y;   // 32 x 8
#pragma unroll
    for (int i = 0; i < 32; i += 8)
        ts[ty + i][tx] = Wz[(size_t)(k0 + ty + i) * N + n0 + tx];
    __syncthreads();
#pragma unroll
    for (int i = 0; i < 32; i += 8) {
        int n = n0 + ty + i, k = k0 + tx;
        float v = ts[tx][ty + i];
        __nv_bfloat16 h, l;
        split2(v, h, l);
        size_t base = (size_t)n * 3 * K;
        Tz[base + k] = h;
        Tz[base + K + k] = h;
        Tz[base + 2 * K + k] = l;
    }
}

// ---------------- fp32 SIMT GEMM, 64x64x16 tile (fold: 288 CTAs) -------------
__global__ __launch_bounds__(256, 4)
void gemm_f32s(const float* __restrict__ A, const float* __restrict__ Bm,
               float* __restrict__ Cd, int M, int Nn, int K,
               long long bStride, long long cStride)
{
    __shared__ float As[2][16][68];
    __shared__ float Bs[2][16][64];
    int tid = threadIdx.x;
    int rowStart = blockIdx.y * 64;
    int colStart = blockIdx.x * 64;
    const float* Bz = Bm + (long long)blockIdx.z * bStride;
    float* Cz = Cd + (long long)blockIdx.z * cStride;

    float4 aP, bP;
    auto gload = [&](int kt) {
        int r = tid >> 2, k4 = (tid & 3) << 2;
        aP = *reinterpret_cast<const float4*>(A + (size_t)(rowStart + r) * K + kt * 16 + k4);
        int br = tid >> 4, bc = (tid & 15) << 2;
        bP = *reinterpret_cast<const float4*>(Bz + (size_t)(kt * 16 + br) * Nn + colStart + bc);
    };
    auto sstore = [&](int buf) {
        int r = tid >> 2, k4 = (tid & 3) << 2;
        As[buf][k4 + 0][r] = aP.x;
        As[buf][k4 + 1][r] = aP.y;
        As[buf][k4 + 2][r] = aP.z;
        As[buf][k4 + 3][r] = aP.w;
        int br = tid >> 4, bc = (tid & 15) << 2;
        *reinterpret_cast<float4*>(&Bs[buf][br][bc]) = bP;
    };

    int tm = (tid >> 4) << 2;
    int tn = (tid & 15) << 2;
    float acc[4][4] = {};

    int nk = K / 16;
    gload(0); sstore(0); __syncthreads();
    for (int kt = 0; kt < nk; kt++) {
        int buf = kt & 1;
        if (kt + 1 < nk) gload(kt + 1);
#pragma unroll
        for (int k = 0; k < 16; k++) {
            float a[4], bfr[4];
            *(float4*)&a[0]   = *(const float4*)&As[buf][k][tm];
            *(float4*)&bfr[0] = *(const float4*)&Bs[buf][k][tn];
#pragma unroll
            for (int i = 0; i < 4; i++)
#pragma unroll
                for (int j = 0; j < 4; j++)
                    acc[i][j] = fmaf(a[i], bfr[j], acc[i][j]);
        }
        if (kt + 1 < nk) sstore((kt + 1) & 1);
        __syncthreads();
    }
#pragma unroll
    for (int i = 0; i < 4; i++) {
        size_t ro = (size_t)(rowStart + tm + i) * Nn + colStart + tn;
        *(float4*)(Cz + ro) = *(float4*)&acc[i][0];
    }
}

// ---------------- HMMA bf16-split GEMM (R8-proven) ---------------------------
// C[m,n] = sum_k A[m,ka(k)]*B[n,k], logical K = Kp = 3*Kc.
// A physical width 2*Kc (hi|lo); k-block remap: ka = k < 2Kc ? k : k-2Kc.
// B physical width Kp (hi|hi|lo). CTA 128x128x64, 128 threads (4 warps x 64x64).
// 3-stage cp.async pipeline; sync order: CP_WAIT -> bar -> mma -> bar.
// MODE 0: fp32 C; MODE 1: C = acc+bias+res(fp32); MODE 2: gelu(acc+bias) split [hi|lo];
// MODE 3: C = acc+bias+resS(hi)+resS(lo)  (residual from split-bf16 buffer, width 2*Nn)
#define MM_STAGES 3
#define MM_STAGE_B 32768            // A 16KB + B 16KB
#define MM_SMEM (MM_STAGES*MM_STAGE_B)

__device__ __forceinline__ void mm_load(uint32_t buf, const __nv_bfloat16* aSrc, int aStride,
                                        const __nv_bfloat16* bSrc, int bStride, int tid)
{
#pragma unroll
    for (int i = 0; i < 8; i++) {
        int idx = tid + i * 128;
        int row = idx >> 3, c = idx & 7;
        uint32_t so = (uint32_t)(row * 128 + ((c ^ (row & 7)) << 4));
        cpasync16(buf + so, aSrc + (size_t)row * aStride + c * 8);
        cpasync16(buf + 16384 + so, bSrc + (size_t)row * bStride + c * 8);
    }
}

template<int MODE>
__global__ __launch_bounds__(128, 2)
void gemm_mma(const __nv_bfloat16* __restrict__ A, const __nv_bfloat16* __restrict__ B,
              const float* __restrict__ bias, const float* __restrict__ res,
              const __nv_bfloat16* __restrict__ resS,
              float* __restrict__ C, __nv_bfloat16* __restrict__ Csplit,
              int Nn, int Kp, int nOut, long long bBatchStride)
{
    extern __shared__ char smem[];
    uint32_t sb = smem_to_u32(smem);
    int tid = threadIdx.x;
    int wid = tid >> 5, lane = tid & 31;
    int wm = wid & 1, wn = wid >> 1;          // warp grid 2x2, tile 64x64

    int Kc = Kp / 3;
    int AS = 2 * Kc;
    int rowStart = blockIdx.y * 128;
    int colStart = blockIdx.x * 128;
    const __nv_bfloat16* Ab = A + (size_t)rowStart * AS;
    const __nv_bfloat16* Bb = B + (size_t)colStart * Kp;
    if (bBatchStride) Bb += (long long)(rowStart >> 12) * bBatchStride;

    float acc[4][8][4];
#pragma unroll
    for (int i = 0; i < 4; i++)
#pragma unroll
        for (int j = 0; j < 8; j++)
#pragma unroll
            for (int q = 0; q < 4; q++) acc[i][j][q] = 0.f;

    int aRow[4], bRow[4];
#pragma unroll
    for (int mt = 0; mt < 4; mt++) aRow[mt] = wm * 64 + mt * 16 + (lane & 15);
    int aHi = (lane >> 4) & 1;
#pragma unroll
    for (int p = 0; p < 4; p++) bRow[p] = wn * 64 + p * 16 + (lane & 7) + ((lane & 16) ? 8 : 0);
    int bHi = (lane >> 3) & 1;

    int NTk = Kp / 64;
    auto loadTile = [&](int kt) {
        int kk = kt * 64;
        int akk = (kk < AS) ? kk : kk - AS;   // remap third block back onto hi
        mm_load(sb + (kt % MM_STAGES) * MM_STAGE_B, Ab + akk, AS, Bb + kk, Kp, tid);
        CP_COMMIT();
    };

    loadTile(0);
    loadTile(1);

    for (int kt = 0; kt < NTk; kt++) {
        if (kt + 2 < NTk) {
            loadTile(kt + 2);
            CP_WAIT(2);                        // tile kt complete (own groups)
        } else if (kt + 2 == NTk) {
            CP_WAIT(1);
        } else {
            CP_WAIT(0);
        }
        __syncthreads();                       // tile kt visible to all warps

        uint32_t aB = sb + (kt % MM_STAGES) * MM_STAGE_B;
        uint32_t bB = aB + 16384;
#pragma unroll
        for (int ks = 0; ks < 4; ks++) {
            uint32_t af[4][4], bf[4][4];
#pragma unroll
            for (int mt = 0; mt < 4; mt++) {
                int r = aRow[mt];
                ldsm4(af[mt], aB + r * 128 + (((2 * ks + aHi) ^ (r & 7)) << 4));
            }
#pragma unroll
            for (int p = 0; p < 4; p++) {
                int r = bRow[p];
                ldsm4(bf[p], bB + r * 128 + (((2 * ks + bHi) ^ (r & 7)) << 4));
            }
#pragma unroll
            for (int mt = 0; mt < 4; mt++)
#pragma unroll
                for (int nt = 0; nt < 8; nt++)
                    hmma(acc[mt][nt], af[mt], bf[nt >> 1][(nt & 1) * 2], bf[nt >> 1][(nt & 1) * 2 + 1]);
        }
        __syncthreads();                       // readers done before next overwrite
    }

    // epilogue
    int rBase = rowStart + wm * 64 + (lane >> 2);
    int cBase = colStart + wn * 64 + (lane & 3) * 2;
#pragma unroll
    for (int mt = 0; mt < 4; mt++) {
#pragma unroll
        for (int half = 0; half < 2; half++) {
            int r = rBase + mt * 16 + half * 8;
#pragma unroll
            for (int nt = 0; nt < 8; nt++) {
                int col = cBase + nt * 8;
                float v0 = acc[mt][nt][half * 2 + 0];
                float v1 = acc[mt][nt][half * 2 + 1];
                if (MODE == 0) {
                    float2 v = make_float2(v0, v1);
                    *(float2*)(C + (size_t)r * Nn + col) = v;
                } else if (MODE == 1) {
                    size_t off = (size_t)r * Nn + col;
                    float2 rv = *(const float2*)(res + off);
                    float2 v = make_float2(v0 + bias[col] + rv.x, v1 + bias[col + 1] + rv.y);
                    *(float2*)(C + off) = v;
                } else if (MODE == 3) {
                    size_t rb = (size_t)r * (2 * Nn) + col;
                    __nv_bfloat162 hh = *(const __nv_bfloat162*)(resS + rb);
                    __nv_bfloat162 ll = *(const __nv_bfloat162*)(resS + rb + Nn);
                    float r0 = __bfloat162float(hh.x) + __bfloat162float(ll.x);
                    float r1 = __bfloat162float(hh.y) + __bfloat162float(ll.y);
                    float2 v = make_float2(v0 + bias[col] + r0, v1 + bias[col + 1] + r1);
                    *(float2*)(C + (size_t)r * Nn + col) = v;
                } else {
                    v0 += bias[col];
                    v1 += bias[col + 1];
                    v0 = 0.5f * v0 * (1.f + erff(v0 * 0.70710678118654752f));
                    v1 = 0.5f * v1 * (1.f + erff(v1 * 0.70710678118654752f));
                    __nv_bfloat16 h0, l0, h1, l1;
                    split2(v0, h0, l0);
                    split2(v1, h1, l1);
                    __nv_bfloat162 hh; hh.x = h0; hh.y = h1;
                    __nv_bfloat162 ll; ll.x = l0; ll.y = l1;
                    size_t mb = (size_t)r * 2 * nOut + col;
                    *(__nv_bfloat162*)(Csplit + mb)        = hh;   // hi
                    *(__nv_bfloat162*)(Csplit + mb + nOut) = ll;   // lo
                }
            }
        }
    }
}

// ---------------- launcher ---------------------------------------------------
extern "C" void kernel_launch(void* const* d_in, const int* in_sizes, int n_in,
                              void* d_out, int out_size)
{
    const float* x   = (const float*)d_in[0];
    const float* src = (const float*)d_in[1];
    const float* c0w = (const float*)d_in[4];
    const float* c0b = (const float*)d_in[5];
    const float* c1w = (const float*)d_in[6];
    const float* c1b = (const float*)d_in[7];
    const float* n1g = (const float*)d_in[8];
    const float* n1b = (const float*)d_in[9];
    const float* qw  = (const float*)d_in[10];
    const float* kvw = (const float*)d_in[11];
    const float* pw  = (const float*)d_in[12];
    const float* pb  = (const float*)d_in[13];
    const float* n2g = (const float*)d_in[14];
    const float* n2b = (const float*)d_in[15];
    const float* f1w = (const float*)d_in[16];
    const float* f1b = (const float*)d_in[17];
    const float* f2w = (const float*)d_in[18];
    const float* f2b = (const float*)d_in[19];
    float* out = (float*)d_out;

    float *kvF, *attnP, *attn, *weff, *w2F, *x2F, *x3F;
    __nv_bfloat16 *xnS, *snS, *w2T, *kvwT, *f1wT, *f2wT, *ln2S, *h1S;
    cudaGetSymbolAddress((void**)&xnS, g_xnS);
    cudaGetSymbolAddress((void**)&snS, g_snS);
    cudaGetSymbolAddress((void**)&kvF, g_kvF);
    cudaGetSymbolAddress((void**)&attnP, g_attnP);
    cudaGetSymbolAddress((void**)&attn, g_attn);
    cudaGetSymbolAddress((void**)&weff, g_weff);
    cudaGetSymbolAddress((void**)&w2F, g_w2F);
    cudaGetSymbolAddress((void**)&w2T, g_w2T);
    cudaGetSymbolAddress((void**)&kvwT, g_kvwT);
    cudaGetSymbolAddress((void**)&f1wT, g_f1wT);
    cudaGetSymbolAddress((void**)&f2wT, g_f2wT);
    cudaGetSymbolAddress((void**)&x2F, g_x2F);
    cudaGetSymbolAddress((void**)&x3F, g_x3F);
    cudaGetSymbolAddress((void**)&ln2S, g_ln2S);
    cudaGetSymbolAddress((void**)&h1S, g_h1S);

    cudaFuncSetAttribute(gemm_mma<0>, cudaFuncAttributeMaxDynamicSharedMemorySize, MM_SMEM);
    cudaFuncSetAttribute(gemm_mma<1>, cudaFuncAttributeMaxDynamicSharedMemorySize, MM_SMEM);
    cudaFuncSetAttribute(gemm_mma<2>, cudaFuncAttributeMaxDynamicSharedMemorySize, MM_SMEM);
    cudaFuncSetAttribute(gemm_mma<3>, cudaFuncAttributeMaxDynamicSharedMemorySize, MM_SMEM);

    dim3 tb(32, 8);

    // idx 0: cpe0 + LN1 on x AND source (merged; -> xnS, snS)
    cpe_ln_dual_kernel<<<dim3(BN / 4, 2), 128>>>(x, src, c0w, c0b, n1g, n1b, xnS, snS);
    // idx 1: kv weight split
    splitT_kernel<<<dim3(2 * CC / 32, CC / 32), tb>>>(kvw, kvwT, CC, 2 * CC, 0, 0);
    // idx 2: fc1 weight split
    splitT_kernel<<<dim3(CHID / 32, CC / 32), tb>>>(f1w, f1wT, CC, CHID, 0, 0);
    // idx 3 (ncu capture target): kv = sn @ kv_w
    gemm_mma<0><<<dim3(2 * CC / 128, BN / 128), 128, MM_SMEM>>>(
        snS, kvwT, nullptr, nullptr, nullptr, kvF, nullptr, 2 * CC, K1, 0, 0);
    // idx 4: logits partials (atomic-free)
    logits_kernel<<<dim3(BB * NH, LSPLIT), 256>>>(kvF, attnP);
    // idx 5: reduce + softmax
    softmax_kernel<<<BB * NH, DD>>>(attnP, attn);
    // idx 6: fc2 weight split
    splitT_kernel<<<dim3(CC / 32, CHID / 32), tb>>>(f2w, f2wT, CHID, CC, 0, 0);

    // fold attn into proj_w, then q_w: W2[b] = q_w @ weff[b]  (64x64 tiles: 288 CTAs)
    weff_kernel<<<BB * NH, 256>>>(attn, pw, weff);
    gemm_f32s<<<dim3(CC / 64, CC / 64, BB), 256>>>(
        qw, weff, w2F, CC, CC, CC, (long long)CC * CC, (long long)CC * CC);
    splitT_kernel<<<dim3(CC / 32, CC / 32, BB), tb>>>(
        w2F, w2T, CC, CC, (long long)CC * CC, (long long)CC * K1);

    // x2 = xn @ W2[b] + proj_b + (xn from split: hi+lo)
    gemm_mma<3><<<dim3(CC / 128, BN / 128), 128, MM_SMEM>>>(
        xnS, w2T, pb, nullptr, xnS, x2F, nullptr, CC, K1, 0, (long long)CC * K1);

    // cpe1 + LN2 (raw -> x3F, split -> ln2S)
    cpe_ln_kernel<<<BN / 4, 128>>>(x2F, c1w, c1b, n2g, n2b, x3F, ln2S);

    // h1 = gelu(ln2 @ fc1_w + fc1_b)   (split-bf16 out, [hi|lo])
    gemm_mma<2><<<dim3(CHID / 128, BN / 128), 128, MM_SMEM>>>(
        ln2S, f1wT, f1b, nullptr, nullptr, nullptr, h1S, CHID, K1, CHID, 0);

    // out = h1 @ fc2_w + fc2_b + x3
    gemm_mma<1><<<dim3(CC / 128, BN / 128), 128, MM_SMEM>>>(
        h1S, f2wT, f2b, x3F, nullptr, out, nullptr, CC, K2, 0, 0);
}

// round 13
// speedup vs baseline: 1.3653x; 1.2926x over previous
#include <cuda_runtime.h>
#include <cuda_fp16.h>
#include <math.h>
#include <stdint.h>

// Problem constants
#define BB   8
#define HH   64
#define WW   64
#define NN   4096
#define CC   384
#define NH   8
#define DD   48
#define CHID 1536
#define BN   (BB*NN)
#define BNC  (BN*CC)
#define KP1  (2*CC)        // 768: logical+physical K for C-contractions (fp16 2-term)
#define KP2  (2*CHID)      // 3072: for fc2
#define LSPLIT 8

// ---------------- scratch ----------------------------------------------------
__device__ __half  g_xnS[(size_t)BN*KP1];
__device__ __half  g_snS[(size_t)BN*KP1];
__device__ float   g_kvF[(size_t)BN*2*CC];
__device__ float   g_attnP[(size_t)LSPLIT*BB*NH*DD*DD];
__device__ float   g_attn[BB*NH*DD*DD];
__device__ float   g_weff[BB*CC*CC];
__device__ float   g_w2F[BB*CC*CC];
__device__ __half  g_w2T[(size_t)BB*CC*KP1];
__device__ __half  g_kvwT[(size_t)2*CC*KP1];
__device__ __half  g_f1wT[(size_t)CHID*KP1];
__device__ __half  g_f2wT[(size_t)CC*KP2];
__device__ float   g_x2F[BNC];
__device__ float   g_x3F[BNC];
__device__ __half  g_ln2S[(size_t)BN*KP1];
__device__ __half  g_h1S[(size_t)BN*KP2];

// ---------------- PTX helpers ------------------------------------------------
__device__ __forceinline__ uint32_t smem_to_u32(const void* p) {
    uint32_t a;
    asm("{ .reg .u64 t; cvta.to.shared.u64 t, %1; cvt.u32.u64 %0, t; }" : "=r"(a) : "l"(p));
    return a;
}
__device__ __forceinline__ void cpasync16(uint32_t sa, const void* g) {
    asm volatile("cp.async.cg.shared.global [%0], [%1], 16;" :: "r"(sa), "l"(g));
}
#define CP_COMMIT() asm volatile("cp.async.commit_group;" ::: "memory")
#define CP_WAIT(n)  asm volatile("cp.async.wait_group %0;" :: "n"(n) : "memory")

__device__ __forceinline__ void ldsm4(uint32_t* r, uint32_t addr) {
    asm volatile("ldmatrix.sync.aligned.m8n8.x4.shared.b16 {%0,%1,%2,%3}, [%4];"
        : "=r"(r[0]), "=r"(r[1]), "=r"(r[2]), "=r"(r[3]) : "r"(addr));
}
__device__ __forceinline__ void hmma(float* c, const uint32_t* a, uint32_t b0, uint32_t b1) {
    asm volatile("mma.sync.aligned.m16n8k16.row.col.f32.f16.f16.f32 "
        "{%0,%1,%2,%3}, {%4,%5,%6,%7}, {%8,%9}, {%0,%1,%2,%3};"
        : "+f"(c[0]), "+f"(c[1]), "+f"(c[2]), "+f"(c[3])
        : "r"(a[0]), "r"(a[1]), "r"(a[2]), "r"(a[3]), "r"(b0), "r"(b1));
}

__device__ __forceinline__ void split2h(float v, __half& h, __half& l) {
    h = __float2half(v);
    l = __float2half(v - __half2float(h));
}

// ---------------- utility kernels -------------------------------------------
__device__ __forceinline__ float warpRed(float v) {
#pragma unroll
    for (int o = 16; o; o >>= 1) v += __shfl_xor_sync(0xffffffffu, v, o);
    return v;
}

// core of cpe+ln over 4 tokens; writes optional fp32 raw + split-fp16 out [hi|lo]
__device__ __forceinline__ void cpe_ln_body(
    const float* __restrict__ in, const float* __restrict__ w,
    const float* __restrict__ cb, const float* __restrict__ gg,
    const float* __restrict__ bb, float* __restrict__ raw,
    __half* __restrict__ sp, int blk)
{
    int b = blk >> 10;
    int n4 = blk & 1023;
    int y = n4 >> 4;
    int x0 = (n4 & 15) << 2;
    const float* inb = in + (size_t)b * NN * CC;

    float vals[3][4];
#pragma unroll
    for (int i = 0; i < 3; i++) {
        int c = threadIdx.x + i * 128;
        float wv[9];
#pragma unroll
        for (int j = 0; j < 9; j++) wv[j] = w[c * 9 + j];
        float bias0 = cb[c];
        float acc[4] = {bias0, bias0, bias0, bias0};
        float res[4];
#pragma unroll
        for (int dy = -1; dy <= 1; dy++) {
            int yy = y + dy;
            if ((unsigned)yy >= HH) continue;
            float v[6];
#pragma unroll
            for (int j = 0; j < 6; j++) {
                int xc = x0 - 1 + j;
                v[j] = ((unsigned)xc < WW) ? inb[((size_t)yy * WW + xc) * CC + c] : 0.f;
            }
            int wb = (dy + 1) * 3;
#pragma unroll
            for (int t = 0; t < 4; t++)
                acc[t] += v[t] * wv[wb] + v[t + 1] * wv[wb + 1] + v[t + 2] * wv[wb + 2];
            if (dy == 0) {
#pragma unroll
                for (int t = 0; t < 4; t++) res[t] = v[t + 1];
            }
        }
#pragma unroll
        for (int t = 0; t < 4; t++) vals[i][t] = acc[t] + res[t];
    }

    float s[4], q[4];
#pragma unroll
    for (int t = 0; t < 4; t++) {
        s[t] = vals[0][t] + vals[1][t] + vals[2][t];
        q[t] = vals[0][t] * vals[0][t] + vals[1][t] * vals[1][t] + vals[2][t] * vals[2][t];
        s[t] = warpRed(s[t]);
        q[t] = warpRed(q[t]);
    }
    __shared__ float rs[4][4], rq[4][4];
    int lane = threadIdx.x & 31, wp = threadIdx.x >> 5;
    if (!lane) {
#pragma unroll
        for (int t = 0; t < 4; t++) { rs[wp][t] = s[t]; rq[wp][t] = q[t]; }
    }
    __syncthreads();
    float mu[4], inv[4];
#pragma unroll
    for (int t = 0; t < 4; t++) {
        float tot = rs[0][t] + rs[1][t] + rs[2][t] + rs[3][t];
        float tq  = rq[0][t] + rq[1][t] + rq[2][t] + rq[3][t];
        mu[t] = tot * (1.f / CC);
        float var = tq * (1.f / CC) - mu[t] * mu[t];
        inv[t] = rsqrtf(var + 1e-5f);
    }

    size_t tokBase = (size_t)b * NN + (size_t)y * WW + x0;
#pragma unroll
    for (int i = 0; i < 3; i++) {
        int c = threadIdx.x + i * 128;
        float g = gg[c], be = bb[c];
#pragma unroll
        for (int t = 0; t < 4; t++) {
            size_t tok = tokBase + t;
            if (raw) raw[tok * CC + c] = vals[i][t];
            float v = (vals[i][t] - mu[t]) * inv[t] * g + be;
            __half h, l;
            split2h(v, h, l);
            sp[tok * KP1 + c] = h;
            sp[tok * KP1 + CC + c] = l;
        }
    }
}

// dual cpe0+LN1: blockIdx.y = 0 -> x -> xnS ; 1 -> source -> snS
__global__ void cpe_ln_dual_kernel(const float* __restrict__ x, const float* __restrict__ src,
                                   const float* __restrict__ w, const float* __restrict__ cb,
                                   const float* __restrict__ gg, const float* __restrict__ bb,
                                   __half* __restrict__ xnS, __half* __restrict__ snS)
{
    if (blockIdx.y == 0)
        cpe_ln_body(x, w, cb, gg, bb, nullptr, xnS, blockIdx.x);
    else
        cpe_ln_body(src, w, cb, gg, bb, nullptr, snS, blockIdx.x);
}

__global__ void cpe_ln_kernel(const float* __restrict__ in, const float* __restrict__ w,
                              const float* __restrict__ cb, const float* __restrict__ gg,
                              const float* __restrict__ bb, float* __restrict__ raw,
                              __half* __restrict__ sp)
{
    cpe_ln_body(in, w, cb, gg, bb, raw, sp, blockIdx.x);
}

// logits partials: P[s][b,h,d,e] = sum_{n in slice s} k[n,d]*v[n,e]  (no atomics)
__global__ void logits_kernel(const float* __restrict__ kv, float* __restrict__ part)
{
    int bh = blockIdx.x;
    int b = bh >> 3, h = bh & 7;
    const float* kb = kv + (size_t)b * NN * (2 * CC) + h * DD;
    const float* vb = kb + CC;
    __shared__ float ks[32][DD], vs[32][DD];
    int d0 = (threadIdx.x >> 4) * 3, e0 = (threadIdx.x & 15) * 3;
    float acc[3][3] = {};
    int n0 = blockIdx.y * (NN / LSPLIT);
    for (int nc = 0; nc < NN / LSPLIT; nc += 32) {
        for (int idx = threadIdx.x; idx < 32 * DD; idx += 256) {
            int r = idx / DD, c = idx % DD;
            size_t off = (size_t)(n0 + nc + r) * (2 * CC) + c;
            ks[r][c] = kb[off];
            vs[r][c] = vb[off];
        }
        __syncthreads();
#pragma unroll 8
        for (int r = 0; r < 32; r++) {
            float k0 = ks[r][d0], k1 = ks[r][d0 + 1], k2 = ks[r][d0 + 2];
            float v0 = vs[r][e0], v1 = vs[r][e0 + 1], v2 = vs[r][e0 + 2];
            acc[0][0] += k0 * v0; acc[0][1] += k0 * v1; acc[0][2] += k0 * v2;
            acc[1][0] += k1 * v0; acc[1][1] += k1 * v1; acc[1][2] += k1 * v2;
            acc[2][0] += k2 * v0; acc[2][1] += k2 * v1; acc[2][2] += k2 * v2;
        }
        __syncthreads();
    }
    float* P = part + ((size_t)blockIdx.y * BB * NH + bh) * DD * DD;
#pragma unroll
    for (int i = 0; i < 3; i++)
#pragma unroll
        for (int j = 0; j < 3; j++)
            P[(d0 + i) * DD + (e0 + j)] = acc[i][j];
}

// reduce partials + softmax over last dim (48), scale = d^-0.5
__global__ void softmax_kernel(const float* __restrict__ part, float* __restrict__ attn)
{
    int bh = blockIdx.x;
    size_t rowOff = (size_t)bh * DD * DD + threadIdx.x * DD;
    const float scale = 0.14433756729740643f;
    float r[DD];
#pragma unroll
    for (int e = 0; e < DD; e++) r[e] = 0.f;
    for (int s = 0; s < LSPLIT; s++) {
        const float* P = part + (size_t)s * BB * NH * DD * DD + rowOff;
#pragma unroll
        for (int e = 0; e < DD; e++) r[e] += P[e];
    }
    float mx = -1e30f;
#pragma unroll
    for (int e = 0; e < DD; e++) { r[e] *= scale; mx = fmaxf(mx, r[e]); }
    float s = 0.f;
#pragma unroll
    for (int e = 0; e < DD; e++) { r[e] = expf(r[e] - mx); s += r[e]; }
    float inv = 1.f / s;
    float* L = attn + rowOff;
#pragma unroll
    for (int e = 0; e < DD; e++) L[e] = r[e] * inv;
}

__global__ void weff_kernel(const float* __restrict__ attn, const float* __restrict__ pw,
                            float* __restrict__ weff)
{
    int b = blockIdx.x >> 3, h = blockIdx.x & 7;
    __shared__ float as[DD][DD];
    __shared__ float ps[DD][64];
    const float* A = attn + (size_t)blockIdx.x * DD * DD;
    for (int idx = threadIdx.x; idx < DD * DD; idx += 256) as[idx / DD][idx % DD] = A[idx];
    int jj = threadIdx.x & 63;
    int e0 = (threadIdx.x >> 6) * 12;
    for (int j0 = 0; j0 < CC; j0 += 64) {
        __syncthreads();
        for (int idx = threadIdx.x; idx < DD * 64; idx += 256) {
            int d = idx >> 6, j = idx & 63;
            ps[d][j] = pw[(size_t)(h * DD + d) * CC + j0 + j];
        }
        __syncthreads();
        for (int ei = 0; ei < 12; ei++) {
            int e = e0 + ei;
            float acc = 0.f;
#pragma unroll
            for (int d = 0; d < DD; d++) acc += as[d][e] * ps[d][jj];
            weff[((size_t)b * CC + h * DD + e) * CC + j0 + jj] = acc;
        }
    }
}

// transpose + fp16 round: W fp32 [K,N] -> T fp16 [N,2K] duplicated [W|W]; batched over z
__global__ void splitT_kernel(const float* __restrict__ W, __half* __restrict__ T,
                              int K, int N, long long wStride, long long tStride)
{
    __shared__ float ts[32][33];
    const float* Wz = W + (long long)blockIdx.z * wStride;
    __half* Tz = T + (long long)blockIdx.z * tStride;
    int k0 = blockIdx.y * 32, n0 = blockIdx.x * 32;
    int tx = threadIdx.x, ty = threadIdx.y;   // 32 x 8
#pragma unroll
    for (int i = 0; i < 32; i += 8)
        ts[ty + i][tx] = Wz[(size_t)(k0 + ty + i) * N + n0 + tx];
    __syncthreads();
#pragma unroll
    for (int i = 0; i < 32; i += 8) {
        int n = n0 + ty + i, k = k0 + tx;
        __half h = __float2half(ts[tx][ty + i]);
        size_t base = (size_t)n * 2 * K;
        Tz[base + k] = h;
        Tz[base + K + k] = h;
    }
}

// ---------------- fp32 SIMT GEMM, 64x64x16 tile (fold: 288 CTAs) -------------
__global__ __launch_bounds__(256, 4)
void gemm_f32s(const float* __restrict__ A, const float* __restrict__ Bm,
               float* __restrict__ Cd, int M, int Nn, int K,
               long long bStride, long long cStride)
{
    __shared__ float As[2][16][68];
    __shared__ float Bs[2][16][64];
    int tid = threadIdx.x;
    int rowStart = blockIdx.y * 64;
    int colStart = blockIdx.x * 64;
    const float* Bz = Bm + (long long)blockIdx.z * bStride;
    float* Cz = Cd + (long long)blockIdx.z * cStride;

    float4 aP, bP;
    auto gload = [&](int kt) {
        int r = tid >> 2, k4 = (tid & 3) << 2;
        aP = *reinterpret_cast<const float4*>(A + (size_t)(rowStart + r) * K + kt * 16 + k4);
        int br = tid >> 4, bc = (tid & 15) << 2;
        bP = *reinterpret_cast<const float4*>(Bz + (size_t)(kt * 16 + br) * Nn + colStart + bc);
    };
    auto sstore = [&](int buf) {
        int r = tid >> 2, k4 = (tid & 3) << 2;
        As[buf][k4 + 0][r] = aP.x;
        As[buf][k4 + 1][r] = aP.y;
        As[buf][k4 + 2][r] = aP.z;
        As[buf][k4 + 3][r] = aP.w;
        int br = tid >> 4, bc = (tid & 15) << 2;
        *reinterpret_cast<float4*>(&Bs[buf][br][bc]) = bP;
    };

    int tm = (tid >> 4) << 2;
    int tn = (tid & 15) << 2;
    float acc[4][4] = {};

    int nk = K / 16;
    gload(0); sstore(0); __syncthreads();
    for (int kt = 0; kt < nk; kt++) {
        int buf = kt & 1;
        if (kt + 1 < nk) gload(kt + 1);
#pragma unroll
        for (int k = 0; k < 16; k++) {
            float a[4], bfr[4];
            *(float4*)&a[0]   = *(const float4*)&As[buf][k][tm];
            *(float4*)&bfr[0] = *(const float4*)&Bs[buf][k][tn];
#pragma unroll
            for (int i = 0; i < 4; i++)
#pragma unroll
                for (int j = 0; j < 4; j++)
                    acc[i][j] = fmaf(a[i], bfr[j], acc[i][j]);
        }
        if (kt + 1 < nk) sstore((kt + 1) & 1);
        __syncthreads();
    }
#pragma unroll
    for (int i = 0; i < 4; i++) {
        size_t ro = (size_t)(rowStart + tm + i) * Nn + colStart + tn;
        *(float4*)(Cz + ro) = *(float4*)&acc[i][0];
    }
}

// ---------------- HMMA fp16 2-term GEMM (R8-proven core) ---------------------
// C[m,n] = sum_k A[m,k]*B[n,k] over physical K = Kp (A = [hi|lo], B = [W|W]).
// CTA 128x128x64, 128 threads (4 warps x 64x64). 3-stage cp.async pipeline;
// sync order: CP_WAIT -> bar -> mma -> bar.
// MODE 0: fp32 C; MODE 1: C = acc+bias+res(fp32); MODE 2: gelu(acc+bias) split [hi|lo];
// MODE 3: C = acc+bias+resS(hi)+resS(lo)  (residual from split-fp16 buffer, width 2*Nn)
#define MM_STAGES 3
#define MM_STAGE_B 32768            // A 16KB + B 16KB
#define MM_SMEM (MM_STAGES*MM_STAGE_B)

__device__ __forceinline__ void mm_load(uint32_t buf, const __half* aSrc, int aStride,
                                        const __half* bSrc, int bStride, int tid)
{
#pragma unroll
    for (int i = 0; i < 8; i++) {
        int idx = tid + i * 128;
        int row = idx >> 3, c = idx & 7;
        uint32_t so = (uint32_t)(row * 128 + ((c ^ (row & 7)) << 4));
        cpasync16(buf + so, aSrc + (size_t)row * aStride + c * 8);
        cpasync16(buf + 16384 + so, bSrc + (size_t)row * bStride + c * 8);
    }
}

template<int MODE>
__global__ __launch_bounds__(128, 2)
void gemm_mma(const __half* __restrict__ A, const __half* __restrict__ B,
              const float* __restrict__ bias, const float* __restrict__ res,
              const __half* __restrict__ resS,
              float* __restrict__ C, __half* __restrict__ Csplit,
              int Nn, int Kp, int nOut, long long bBatchStride)
{
    extern __shared__ char smem[];
    uint32_t sb = smem_to_u32(smem);
    int tid = threadIdx.x;
    int wid = tid >> 5, lane = tid & 31;
    int wm = wid & 1, wn = wid >> 1;          // warp grid 2x2, tile 64x64

    int rowStart = blockIdx.y * 128;
    int colStart = blockIdx.x * 128;
    const __half* Ab = A + (size_t)rowStart * Kp;
    const __half* Bb = B + (size_t)colStart * Kp;
    if (bBatchStride) Bb += (long long)(rowStart >> 12) * bBatchStride;

    float acc[4][8][4];
#pragma unroll
    for (int i = 0; i < 4; i++)
#pragma unroll
        for (int j = 0; j < 8; j++)
#pragma unroll
            for (int q = 0; q < 4; q++) acc[i][j][q] = 0.f;

    int aRow[4], bRow[4];
#pragma unroll
    for (int mt = 0; mt < 4; mt++) aRow[mt] = wm * 64 + mt * 16 + (lane & 15);
    int aHi = (lane >> 4) & 1;
#pragma unroll
    for (int p = 0; p < 4; p++) bRow[p] = wn * 64 + p * 16 + (lane & 7) + ((lane & 16) ? 8 : 0);
    int bHi = (lane >> 3) & 1;

    int NTk = Kp / 64;
    auto loadTile = [&](int kt) {
        int kk = kt * 64;
        mm_load(sb + (kt % MM_STAGES) * MM_STAGE_B, Ab + kk, Kp, Bb + kk, Kp, tid);
        CP_COMMIT();
    };

    loadTile(0);
    loadTile(1);

    for (int kt = 0; kt < NTk; kt++) {
        if (kt + 2 < NTk) {
            loadTile(kt + 2);
            CP_WAIT(2);                        // tile kt complete (own groups)
        } else if (kt + 2 == NTk) {
            CP_WAIT(1);
        } else {
            CP_WAIT(0);
        }
        __syncthreads();                       // tile kt visible to all warps

        uint32_t aB = sb + (kt % MM_STAGES) * MM_STAGE_B;
        uint32_t bB = aB + 16384;
#pragma unroll
        for (int ks = 0; ks < 4; ks++) {
            uint32_t af[4][4], bf[4][4];
#pragma unroll
            for (int mt = 0; mt < 4; mt++) {
                int r = aRow[mt];
                ldsm4(af[mt], aB + r * 128 + (((2 * ks + aHi) ^ (r & 7)) << 4));
            }
#pragma unroll
            for (int p = 0; p < 4; p++) {
                int r = bRow[p];
                ldsm4(bf[p], bB + r * 128 + (((2 * ks + bHi) ^ (r & 7)) << 4));
            }
#pragma unroll
            for (int mt = 0; mt < 4; mt++)
#pragma unroll
                for (int nt = 0; nt < 8; nt++)
                    hmma(acc[mt][nt], af[mt], bf[nt >> 1][(nt & 1) * 2], bf[nt >> 1][(nt & 1) * 2 + 1]);
        }
        __syncthreads();                       // readers done before next overwrite
    }

    // epilogue
    int rBase = rowStart + wm * 64 + (lane >> 2);
    int cBase = colStart + wn * 64 + (lane & 3) * 2;
#pragma unroll
    for (int mt = 0; mt < 4; mt++) {
#pragma unroll
        for (int half = 0; half < 2; half++) {
            int r = rBase + mt * 16 + half * 8;
#pragma unroll
            for (int nt = 0; nt < 8; nt++) {
                int col = cBase + nt * 8;
                float v0 = acc[mt][nt][half * 2 + 0];
                float v1 = acc[mt][nt][half * 2 + 1];
                if (MODE == 0) {
                    float2 v = make_float2(v0, v1);
                    *(float2*)(C + (size_t)r * Nn + col) = v;
                } else if (MODE == 1) {
                    size_t off = (size_t)r * Nn + col;
                    float2 rv = *(const float2*)(res + off);
                    float2 v = make_float2(v0 + bias[col] + rv.x, v1 + bias[col + 1] + rv.y);
                    *(float2*)(C + off) = v;
                } else if (MODE == 3) {
                    size_t rb = (size_t)r * (2 * Nn) + col;
                    __half2 hh = *(const __half2*)(resS + rb);
                    __half2 ll = *(const __half2*)(resS + rb + Nn);
                    float r0 = __half2float(hh.x) + __half2float(ll.x);
                    float r1 = __half2float(hh.y) + __half2float(ll.y);
                    float2 v = make_float2(v0 + bias[col] + r0, v1 + bias[col + 1] + r1);
                    *(float2*)(C + (size_t)r * Nn + col) = v;
                } else {
                    v0 += bias[col];
                    v1 += bias[col + 1];
                    v0 = 0.5f * v0 * (1.f + erff(v0 * 0.70710678118654752f));
                    v1 = 0.5f * v1 * (1.f + erff(v1 * 0.70710678118654752f));
                    __half h0, l0, h1, l1;
                    split2h(v0, h0, l0);
                    split2h(v1, h1, l1);
                    __half2 hh; hh.x = h0; hh.y = h1;
                    __half2 ll; ll.x = l0; ll.y = l1;
                    size_t mb = (size_t)r * 2 * nOut + col;
                    *(__half2*)(Csplit + mb)        = hh;   // hi
                    *(__half2*)(Csplit + mb + nOut) = ll;   // lo
                }
            }
        }
    }
}

// ---------------- launcher ---------------------------------------------------
extern "C" void kernel_launch(void* const* d_in, const int* in_sizes, int n_in,
                              void* d_out, int out_size)
{
    const float* x   = (const float*)d_in[0];
    const float* src = (const float*)d_in[1];
    const float* c0w = (const float*)d_in[4];
    const float* c0b = (const float*)d_in[5];
    const float* c1w = (const float*)d_in[6];
    const float* c1b = (const float*)d_in[7];
    const float* n1g = (const float*)d_in[8];
    const float* n1b = (const float*)d_in[9];
    const float* qw  = (const float*)d_in[10];
    const float* kvw = (const float*)d_in[11];
    const float* pw  = (const float*)d_in[12];
    const float* pb  = (const float*)d_in[13];
    const float* n2g = (const float*)d_in[14];
    const float* n2b = (const float*)d_in[15];
    const float* f1w = (const float*)d_in[16];
    const float* f1b = (const float*)d_in[17];
    const float* f2w = (const float*)d_in[18];
    const float* f2b = (const float*)d_in[19];
    float* out = (float*)d_out;

    float *kvF, *attnP, *attn, *weff, *w2F, *x2F, *x3F;
    __half *xnS, *snS, *w2T, *kvwT, *f1wT, *f2wT, *ln2S, *h1S;
    cudaGetSymbolAddress((void**)&xnS, g_xnS);
    cudaGetSymbolAddress((void**)&snS, g_snS);
    cudaGetSymbolAddress((void**)&kvF, g_kvF);
    cudaGetSymbolAddress((void**)&attnP, g_attnP);
    cudaGetSymbolAddress((void**)&attn, g_attn);
    cudaGetSymbolAddress((void**)&weff, g_weff);
    cudaGetSymbolAddress((void**)&w2F, g_w2F);
    cudaGetSymbolAddress((void**)&w2T, g_w2T);
    cudaGetSymbolAddress((void**)&kvwT, g_kvwT);
    cudaGetSymbolAddress((void**)&f1wT, g_f1wT);
    cudaGetSymbolAddress((void**)&f2wT, g_f2wT);
    cudaGetSymbolAddress((void**)&x2F, g_x2F);
    cudaGetSymbolAddress((void**)&x3F, g_x3F);
    cudaGetSymbolAddress((void**)&ln2S, g_ln2S);
    cudaGetSymbolAddress((void**)&h1S, g_h1S);

    cudaFuncSetAttribute(gemm_mma<0>, cudaFuncAttributeMaxDynamicSharedMemorySize, MM_SMEM);
    cudaFuncSetAttribute(gemm_mma<1>, cudaFuncAttributeMaxDynamicSharedMemorySize, MM_SMEM);
    cudaFuncSetAttribute(gemm_mma<2>, cudaFuncAttributeMaxDynamicSharedMemorySize, MM_SMEM);
    cudaFuncSetAttribute(gemm_mma<3>, cudaFuncAttributeMaxDynamicSharedMemorySize, MM_SMEM);

    dim3 tb(32, 8);

    // idx 0: cpe0 + LN1 on x AND source (merged; -> xnS, snS)
    cpe_ln_dual_kernel<<<dim3(BN / 4, 2), 128>>>(x, src, c0w, c0b, n1g, n1b, xnS, snS);
    // idx 1: kv weight transpose (fp16 dup)
    splitT_kernel<<<dim3(2 * CC / 32, CC / 32), tb>>>(kvw, kvwT, CC, 2 * CC, 0, 0);
    // idx 2: fc1 weight transpose
    splitT_kernel<<<dim3(CHID / 32, CC / 32), tb>>>(f1w, f1wT, CC, CHID, 0, 0);
    // idx 3 (ncu capture target): kv = sn @ kv_w
    gemm_mma<0><<<dim3(2 * CC / 128, BN / 128), 128, MM_SMEM>>>(
        snS, kvwT, nullptr, nullptr, nullptr, kvF, nullptr, 2 * CC, KP1, 0, 0);
    // idx 4: logits partials (atomic-free)
    logits_kernel<<<dim3(BB * NH, LSPLIT), 256>>>(kvF, attnP);
    // idx 5: reduce + softmax
    softmax_kernel<<<BB * NH, DD>>>(attnP, attn);
    // idx 6: fc2 weight transpose
    splitT_kernel<<<dim3(CC / 32, CHID / 32), tb>>>(f2w, f2wT, CHID, CC, 0, 0);

    // fold attn into proj_w, then q_w: W2[b] = q_w @ weff[b]
    weff_kernel<<<BB * NH, 256>>>(attn, pw, weff);
    gemm_f32s<<<dim3(CC / 64, CC / 64, BB), 256>>>(
        qw, weff, w2F, CC, CC, CC, (long long)CC * CC, (long long)CC * CC);
    splitT_kernel<<<dim3(CC / 32, CC / 32, BB), tb>>>(
        w2F, w2T, CC, CC, (long long)CC * CC, (long long)CC * KP1);

    // x2 = xn @ W2[b] + proj_b + (xn from split: hi+lo)
    gemm_mma<3><<<dim3(CC / 128, BN / 128), 128, MM_SMEM>>>(
        xnS, w2T, pb, nullptr, xnS, x2F, nullptr, CC, KP1, 0, (long long)CC * KP1);

    // cpe1 + LN2 (raw -> x3F, split -> ln2S)
    cpe_ln_kernel<<<BN / 4, 128>>>(x2F, c1w, c1b, n2g, n2b, x3F, ln2S);

    // h1 = gelu(ln2 @ fc1_w + fc1_b)   (split-fp16 out, [hi|lo])
    gemm_mma<2><<<dim3(CHID / 128, BN / 128), 128, MM_SMEM>>>(
        ln2S, f1wT, f1b, nullptr, nullptr, nullptr, h1S, CHID, KP1, CHID, 0);

    // out = h1 @ fc2_w + fc2_b + x3
    gemm_mma<1><<<dim3(CC / 128, BN / 128), 128, MM_SMEM>>>(
        h1S, f2wT, f2b, x3F, nullptr, out, nullptr, CC, KP2, 0, 0);
}

// round 15
// speedup vs baseline: 1.8959x; 1.3886x over previous
#include <cuda_runtime.h>
#include <cuda_fp16.h>
#include <math.h>
#include <stdint.h>

// Problem constants
#define BB   8
#define HH   64
#define WW   64
#define NN   4096
#define CC   384
#define NH   8
#define DD   48
#define CHID 1536
#define BN   (BB*NN)
#define BNC  (BN*CC)
#define A1   (2*CC)        // xnS physical width [hi|lo] (residual needs lo)
#define LSPLIT 8

// ---------------- scratch ----------------------------------------------------
__device__ __half  g_xnS[(size_t)BN*A1];       // [hi|lo]
__device__ __half  g_snS[(size_t)BN*CC];       // hi only
__device__ float   g_kvF[(size_t)BN*2*CC];
__device__ float   g_attnP[(size_t)LSPLIT*BB*NH*DD*DD];
__device__ float   g_attn[BB*NH*DD*DD];
__device__ float   g_weff[BB*CC*CC];
__device__ float   g_w2F[BB*CC*CC];
__device__ __half  g_w2T[(size_t)BB*CC*CC];
__device__ __half  g_kvwT[(size_t)2*CC*CC];
__device__ __half  g_f1wT[(size_t)CHID*CC];
__device__ __half  g_f2wT[(size_t)CC*CHID];
__device__ float   g_x2F[BNC];
__device__ float   g_x3F[BNC];
__device__ __half  g_ln2S[(size_t)BN*CC];      // hi only
__device__ __half  g_h1S[(size_t)BN*CHID];     // hi only
__device__ float   g_dummy;

// ---------------- PTX helpers ------------------------------------------------
__device__ __forceinline__ uint32_t smem_to_u32(const void* p) {
    uint32_t a;
    asm("{ .reg .u64 t; cvta.to.shared.u64 t, %1; cvt.u32.u64 %0, t; }" : "=r"(a) : "l"(p));
    return a;
}
__device__ __forceinline__ void cpasync16(uint32_t sa, const void* g) {
    asm volatile("cp.async.cg.shared.global [%0], [%1], 16;" :: "r"(sa), "l"(g));
}
#define CP_COMMIT() asm volatile("cp.async.commit_group;" ::: "memory")
#define CP_WAIT(n)  asm volatile("cp.async.wait_group %0;" :: "n"(n) : "memory")

__device__ __forceinline__ void ldsm4(uint32_t* r, uint32_t addr) {
    asm volatile("ldmatrix.sync.aligned.m8n8.x4.shared.b16 {%0,%1,%2,%3}, [%4];"
        : "=r"(r[0]), "=r"(r[1]), "=r"(r[2]), "=r"(r[3]) : "r"(addr));
}
__device__ __forceinline__ void hmma(float* c, const uint32_t* a, uint32_t b0, uint32_t b1) {
    asm volatile("mma.sync.aligned.m16n8k16.row.col.f32.f16.f16.f32 "
        "{%0,%1,%2,%3}, {%4,%5,%6,%7}, {%8,%9}, {%0,%1,%2,%3};"
        : "+f"(c[0]), "+f"(c[1]), "+f"(c[2]), "+f"(c[3])
        : "r"(a[0]), "r"(a[1]), "r"(a[2]), "r"(a[3]), "r"(b0), "r"(b1));
}

__device__ __forceinline__ void split2h(float v, __half& h, __half& l) {
    h = __float2half(v);
    l = __float2half(v - __half2float(h));
}

// ---------------- utility kernels -------------------------------------------
__device__ __forceinline__ float warpRed(float v) {
#pragma unroll
    for (int o = 16; o; o >>= 1) v += __shfl_xor_sync(0xffffffffu, v, o);
    return v;
}

// core of cpe+ln over 4 tokens; writes optional fp32 raw + fp16 out
// spW: row width of sp; storeLo: also write lo block at +CC
__device__ __forceinline__ void cpe_ln_body(
    const float* __restrict__ in, const float* __restrict__ w,
    const float* __restrict__ cb, const float* __restrict__ gg,
    const float* __restrict__ bb, float* __restrict__ raw,
    __half* __restrict__ sp, int spW, bool storeLo, int blk)
{
    int b = blk >> 10;
    int n4 = blk & 1023;
    int y = n4 >> 4;
    int x0 = (n4 & 15) << 2;
    const float* inb = in + (size_t)b * NN * CC;

    float vals[3][4];
#pragma unroll
    for (int i = 0; i < 3; i++) {
        int c = threadIdx.x + i * 128;
        float wv[9];
#pragma unroll
        for (int j = 0; j < 9; j++) wv[j] = w[c * 9 + j];
        float bias0 = cb[c];
        float acc[4] = {bias0, bias0, bias0, bias0};
        float res[4];
#pragma unroll
        for (int dy = -1; dy <= 1; dy++) {
            int yy = y + dy;
            if ((unsigned)yy >= HH) continue;
            float v[6];
#pragma unroll
            for (int j = 0; j < 6; j++) {
                int xc = x0 - 1 + j;
                v[j] = ((unsigned)xc < WW) ? inb[((size_t)yy * WW + xc) * CC + c] : 0.f;
            }
            int wb = (dy + 1) * 3;
#pragma unroll
            for (int t = 0; t < 4; t++)
                acc[t] += v[t] * wv[wb] + v[t + 1] * wv[wb + 1] + v[t + 2] * wv[wb + 2];
            if (dy == 0) {
#pragma unroll
                for (int t = 0; t < 4; t++) res[t] = v[t + 1];
            }
        }
#pragma unroll
        for (int t = 0; t < 4; t++) vals[i][t] = acc[t] + res[t];
    }

    float s[4], q[4];
#pragma unroll
    for (int t = 0; t < 4; t++) {
        s[t] = vals[0][t] + vals[1][t] + vals[2][t];
        q[t] = vals[0][t] * vals[0][t] + vals[1][t] * vals[1][t] + vals[2][t] * vals[2][t];
        s[t] = warpRed(s[t]);
        q[t] = warpRed(q[t]);
    }
    __shared__ float rs[4][4], rq[4][4];
    int lane = threadIdx.x & 31, wp = threadIdx.x >> 5;
    if (!lane) {
#pragma unroll
        for (int t = 0; t < 4; t++) { rs[wp][t] = s[t]; rq[wp][t] = q[t]; }
    }
    __syncthreads();
    float mu[4], inv[4];
#pragma unroll
    for (int t = 0; t < 4; t++) {
        float tot = rs[0][t] + rs[1][t] + rs[2][t] + rs[3][t];
        float tq  = rq[0][t] + rq[1][t] + rq[2][t] + rq[3][t];
        mu[t] = tot * (1.f / CC);
        float var = tq * (1.f / CC) - mu[t] * mu[t];
        inv[t] = rsqrtf(var + 1e-5f);
    }

    size_t tokBase = (size_t)b * NN + (size_t)y * WW + x0;
#pragma unroll
    for (int i = 0; i < 3; i++) {
        int c = threadIdx.x + i * 128;
        float g = gg[c], be = bb[c];
#pragma unroll
        for (int t = 0; t < 4; t++) {
            size_t tok = tokBase + t;
            if (raw) raw[tok * CC + c] = vals[i][t];
            float v = (vals[i][t] - mu[t]) * inv[t] * g + be;
            __half h, l;
            split2h(v, h, l);
            sp[tok * spW + c] = h;
            if (storeLo) sp[tok * spW + CC + c] = l;
        }
    }
}

// dual cpe0+LN1: blockIdx.y = 0 -> x -> xnS [hi|lo] ; 1 -> source -> snS [hi]
__global__ void cpe_ln_dual_kernel(const float* __restrict__ x, const float* __restrict__ src,
                                   const float* __restrict__ w, const float* __restrict__ cb,
                                   const float* __restrict__ gg, const float* __restrict__ bb,
                                   __half* __restrict__ xnS, __half* __restrict__ snS)
{
    if (blockIdx.y == 0)
        cpe_ln_body(x, w, cb, gg, bb, nullptr, xnS, A1, true, blockIdx.x);
    else
        cpe_ln_body(src, w, cb, gg, bb, nullptr, snS, CC, false, blockIdx.x);
}

__global__ void cpe_ln_kernel(const float* __restrict__ in, const float* __restrict__ w,
                              const float* __restrict__ cb, const float* __restrict__ gg,
                              const float* __restrict__ bb, float* __restrict__ raw,
                              __half* __restrict__ sp)
{
    cpe_ln_body(in, w, cb, gg, bb, raw, sp, CC, false, blockIdx.x);
}

// logits partials: P[s][b,h,d,e] = sum_{n in slice s} k[n,d]*v[n,e]  (no atomics)
__global__ void logits_kernel(const float* __restrict__ kv, float* __restrict__ part)
{
    int bh = blockIdx.x;
    int b = bh >> 3, h = bh & 7;
    const float* kb = kv + (size_t)b * NN * (2 * CC) + h * DD;
    const float* vb = kb + CC;
    __shared__ float ks[32][DD], vs[32][DD];
    int d0 = (threadIdx.x >> 4) * 3, e0 = (threadIdx.x & 15) * 3;
    float acc[3][3] = {};
    int n0 = blockIdx.y * (NN / LSPLIT);
    for (int nc = 0; nc < NN / LSPLIT; nc += 32) {
        for (int idx = threadIdx.x; idx < 32 * DD; idx += 256) {
            int r = idx / DD, c = idx % DD;
            size_t off = (size_t)(n0 + nc + r) * (2 * CC) + c;
            ks[r][c] = kb[off];
            vs[r][c] = vb[off];
        }
        __syncthreads();
#pragma unroll 8
        for (int r = 0; r < 32; r++) {
            float k0 = ks[r][d0], k1 = ks[r][d0 + 1], k2 = ks[r][d0 + 2];
            float v0 = vs[r][e0], v1 = vs[r][e0 + 1], v2 = vs[r][e0 + 2];
            acc[0][0] += k0 * v0; acc[0][1] += k0 * v1; acc[0][2] += k0 * v2;
            acc[1][0] += k1 * v0; acc[1][1] += k1 * v1; acc[1][2] += k1 * v2;
            acc[2][0] += k2 * v0; acc[2][1] += k2 * v1; acc[2][2] += k2 * v2;
        }
        __syncthreads();
    }
    float* P = part + ((size_t)blockIdx.y * BB * NH + bh) * DD * DD;
#pragma unroll
    for (int i = 0; i < 3; i++)
#pragma unroll
        for (int j = 0; j < 3; j++)
            P[(d0 + i) * DD + (e0 + j)] = acc[i][j];
}

// reduce partials + softmax over last dim (48), scale = d^-0.5
__global__ void softmax_kernel(const float* __restrict__ part, float* __restrict__ attn)
{
    int bh = blockIdx.x;
    size_t rowOff = (size_t)bh * DD * DD + threadIdx.x * DD;
    const float scale = 0.14433756729740643f;
    float r[DD];
#pragma unroll
    for (int e = 0; e < DD; e++) r[e] = 0.f;
    for (int s = 0; s < LSPLIT; s++) {
        const float* P = part + (size_t)s * BB * NH * DD * DD + rowOff;
#pragma unroll
        for (int e = 0; e < DD; e++) r[e] += P[e];
    }
    float mx = -1e30f;
#pragma unroll
    for (int e = 0; e < DD; e++) { r[e] *= scale; mx = fmaxf(mx, r[e]); }
    float s = 0.f;
#pragma unroll
    for (int e = 0; e < DD; e++) { r[e] = expf(r[e] - mx); s += r[e]; }
    float inv = 1.f / s;
    float* L = attn + rowOff;
#pragma unroll
    for (int e = 0; e < DD; e++) L[e] = r[e] * inv;
}

__global__ void weff_kernel(const float* __restrict__ attn, const float* __restrict__ pw,
                            float* __restrict__ weff)
{
    int b = blockIdx.x >> 3, h = blockIdx.x & 7;
    __shared__ float as[DD][DD];
    __shared__ float ps[DD][64];
    const float* A = attn + (size_t)blockIdx.x * DD * DD;
    for (int idx = threadIdx.x; idx < DD * DD; idx += 256) as[idx / DD][idx % DD] = A[idx];
    int jj = threadIdx.x & 63;
    int e0 = (threadIdx.x >> 6) * 12;
    for (int j0 = 0; j0 < CC; j0 += 64) {
        __syncthreads();
        for (int idx = threadIdx.x; idx < DD * 64; idx += 256) {
            int d = idx >> 6, j = idx & 63;
            ps[d][j] = pw[(size_t)(h * DD + d) * CC + j0 + j];
        }
        __syncthreads();
        for (int ei = 0; ei < 12; ei++) {
            int e = e0 + ei;
            float acc = 0.f;
#pragma unroll
            for (int d = 0; d < DD; d++) acc += as[d][e] * ps[d][jj];
            weff[((size_t)b * CC + h * DD + e) * CC + j0 + jj] = acc;
        }
    }
}

// transpose + fp16 round: W fp32 [K,N] -> T fp16 [N,K]; batched over z
__global__ void splitT_kernel(const float* __restrict__ W, __half* __restrict__ T,
                              int K, int N, long long wStride, long long tStride)
{
    __shared__ float ts[32][33];
    const float* Wz = W + (long long)blockIdx.z * wStride;
    __half* Tz = T + (long long)blockIdx.z * tStride;
    int k0 = blockIdx.y * 32, n0 = blockIdx.x * 32;
    int tx = threadIdx.x, ty = threadIdx.y;   // 32 x 8
#pragma unroll
    for (int i = 0; i < 32; i += 8)
        ts[ty + i][tx] = Wz[(size_t)(k0 + ty + i) * N + n0 + tx];
    __syncthreads();
#pragma unroll
    for (int i = 0; i < 32; i += 8) {
        int n = n0 + ty + i, k = k0 + tx;
        Tz[(size_t)n * K + k] = __float2half(ts[tx][ty + i]);
    }
}

// ---------------- fp32 SIMT GEMM, 64x64x16 tile (fold: 288 CTAs) -------------
__global__ __launch_bounds__(256, 4)
void gemm_f32s(const float* __restrict__ A, const float* __restrict__ Bm,
               float* __restrict__ Cd, int M, int Nn, int K,
               long long bStride, long long cStride)
{
    __shared__ float As[2][16][68];
    __shared__ float Bs[2][16][64];
    int tid = threadIdx.x;
    int rowStart = blockIdx.y * 64;
    int colStart = blockIdx.x * 64;
    const float* Bz = Bm + (long long)blockIdx.z * bStride;
    float* Cz = Cd + (long long)blockIdx.z * cStride;

    float4 aP, bP;
    auto gload = [&](int kt) {
        int r = tid >> 2, k4 = (tid & 3) << 2;
        aP = *reinterpret_cast<const float4*>(A + (size_t)(rowStart + r) * K + kt * 16 + k4);
        int br = tid >> 4, bc = (tid & 15) << 2;
        bP = *reinterpret_cast<const float4*>(Bz + (size_t)(kt * 16 + br) * Nn + colStart + bc);
    };
    auto sstore = [&](int buf) {
        int r = tid >> 2, k4 = (tid & 3) << 2;
        As[buf][k4 + 0][r] = aP.x;
        As[buf][k4 + 1][r] = aP.y;
        As[buf][k4 + 2][r] = aP.z;
        As[buf][k4 + 3][r] = aP.w;
        int br = tid >> 4, bc = (tid & 15) << 2;
        *reinterpret_cast<float4*>(&Bs[buf][br][bc]) = bP;
    };

    int tm = (tid >> 4) << 2;
    int tn = (tid & 15) << 2;
    float acc[4][4] = {};

    int nk = K / 16;
    gload(0); sstore(0); __syncthreads();
    for (int kt = 0; kt < nk; kt++) {
        int buf = kt & 1;
        if (kt + 1 < nk) gload(kt + 1);
#pragma unroll
        for (int k = 0; k < 16; k++) {
            float a[4], bfr[4];
            *(float4*)&a[0]   = *(const float4*)&As[buf][k][tm];
            *(float4*)&bfr[0] = *(const float4*)&Bs[buf][k][tn];
#pragma unroll
            for (int i = 0; i < 4; i++)
#pragma unroll
                for (int j = 0; j < 4; j++)
                    acc[i][j] = fmaf(a[i], bfr[j], acc[i][j]);
        }
        if (kt + 1 < nk) sstore((kt + 1) & 1);
        __syncthreads();
    }
#pragma unroll
    for (int i = 0; i < 4; i++) {
        size_t ro = (size_t)(rowStart + tm + i) * Nn + colStart + tn;
        *(float4*)(Cz + ro) = *(float4*)&acc[i][0];
    }
}

// ---------------- HMMA fp16 single-term GEMM (R8-proven core) ----------------
// C[m,n] = sum_k A[m,k]*B[n,k]; A rows stride aStride (>= Kp), B rows stride Kp.
// CTA 128x128x64, 128 threads (4 warps x 64x64). 3-stage cp.async pipeline.
// MODE 0: fp32 C; MODE 1: C = acc+bias+res(fp32); MODE 2: gelu(acc+bias)->fp16 Csplit;
// MODE 3: C = acc+bias+resS(hi)+resS(lo)  (residual from [hi|lo] fp16 buffer, width 2*Nn)
#define MM_STAGES 3
#define MM_STAGE_B 32768            // A 16KB + B 16KB
#define MM_SMEM (MM_STAGES*MM_STAGE_B)

__device__ __forceinline__ void mm_load(uint32_t buf, const __half* aSrc, int aStride,
                                        const __half* bSrc, int bStride, int tid)
{
#pragma unroll
    for (int i = 0; i < 8; i++) {
        int idx = tid + i * 128;
        int row = idx >> 3, c = idx & 7;
        uint32_t so = (uint32_t)(row * 128 + ((c ^ (row & 7)) << 4));
        cpasync16(buf + so, aSrc + (size_t)row * aStride + c * 8);
        cpasync16(buf + 16384 + so, bSrc + (size_t)row * bStride + c * 8);
    }
}

template<int MODE>
__global__ __launch_bounds__(128, 2)
void gemm_mma(const __half* __restrict__ A, const __half* __restrict__ B,
              const float* __restrict__ bias, const float* __restrict__ res,
              const __half* __restrict__ resS,
              float* __restrict__ C, __half* __restrict__ Csplit,
              int Nn, int Kp, int aStride, int nOut, long long bBatchStride)
{
    extern __shared__ char smem[];
    uint32_t sb = smem_to_u32(smem);
    int tid = threadIdx.x;
    int wid = tid >> 5, lane = tid & 31;
    int wm = wid & 1, wn = wid >> 1;          // warp grid 2x2, tile 64x64

    int rowStart = blockIdx.y * 128;
    int colStart = blockIdx.x * 128;
    const __half* Ab = A + (size_t)rowStart * aStride;
    const __half* Bb = B + (size_t)colStart * Kp;
    if (bBatchStride) Bb += (long long)(rowStart >> 12) * bBatchStride;

    float acc[4][8][4];
#pragma unroll
    for (int i = 0; i < 4; i++)
#pragma unroll
        for (int j = 0; j < 8; j++)
#pragma unroll
            for (int q = 0; q < 4; q++) acc[i][j][q] = 0.f;

    int aRow[4], bRow[4];
#pragma unroll
    for (int mt = 0; mt < 4; mt++) aRow[mt] = wm * 64 + mt * 16 + (lane & 15);
    int aHi = (lane >> 4) & 1;
#pragma unroll
    for (int p = 0; p < 4; p++) bRow[p] = wn * 64 + p * 16 + (lane & 7) + ((lane & 16) ? 8 : 0);
    int bHi = (lane >> 3) & 1;

    int NTk = Kp / 64;
    auto loadTile = [&](int kt) {
        int kk = kt * 64;
        mm_load(sb + (kt % MM_STAGES) * MM_STAGE_B, Ab + kk, aStride, Bb + kk, Kp, tid);
        CP_COMMIT();
    };

    loadTile(0);
    loadTile(1);

    for (int kt = 0; kt < NTk; kt++) {
        if (kt + 2 < NTk) {
            loadTile(kt + 2);
            CP_WAIT(2);                        // tile kt complete (own groups)
        } else if (kt + 2 == NTk) {
            CP_WAIT(1);
        } else {
            CP_WAIT(0);
        }
        __syncthreads();                       // tile kt visible to all warps

        uint32_t aB = sb + (kt % MM_STAGES) * MM_STAGE_B;
        uint32_t bB = aB + 16384;
#pragma unroll
        for (int ks = 0; ks < 4; ks++) {
            uint32_t af[4][4], bf[4][4];
#pragma unroll
            for (int mt = 0; mt < 4; mt++) {
                int r = aRow[mt];
                ldsm4(af[mt], aB + r * 128 + (((2 * ks + aHi) ^ (r & 7)) << 4));
            }
#pragma unroll
            for (int p = 0; p < 4; p++) {
                int r = bRow[p];
                ldsm4(bf[p], bB + r * 128 + (((2 * ks + bHi) ^ (r & 7)) << 4));
            }
#pragma unroll
            for (int mt = 0; mt < 4; mt++)
#pragma unroll
                for (int nt = 0; nt < 8; nt++)
                    hmma(acc[mt][nt], af[mt], bf[nt >> 1][(nt & 1) * 2], bf[nt >> 1][(nt & 1) * 2 + 1]);
        }
        __syncthreads();                       // readers done before next overwrite
    }

    // epilogue
    int rBase = rowStart + wm * 64 + (lane >> 2);
    int cBase = colStart + wn * 64 + (lane & 3) * 2;
#pragma unroll
    for (int mt = 0; mt < 4; mt++) {
#pragma unroll
        for (int half = 0; half < 2; half++) {
            int r = rBase + mt * 16 + half * 8;
#pragma unroll
            for (int nt = 0; nt < 8; nt++) {
                int col = cBase + nt * 8;
                float v0 = acc[mt][nt][half * 2 + 0];
                float v1 = acc[mt][nt][half * 2 + 1];
                if (MODE == 0) {
                    float2 v = make_float2(v0, v1);
                    *(float2*)(C + (size_t)r * Nn + col) = v;
                } else if (MODE == 1) {
                    size_t off = (size_t)r * Nn + col;
                    float2 rv = *(const float2*)(res + off);
                    float2 v = make_float2(v0 + bias[col] + rv.x, v1 + bias[col + 1] + rv.y);
                    *(float2*)(C + off) = v;
                } else if (MODE == 3) {
                    size_t rb = (size_t)r * (2 * Nn) + col;
                    __half2 hh = *(const __half2*)(resS + rb);
                    __half2 ll = *(const __half2*)(resS + rb + Nn);
                    float r0 = __half2float(hh.x) + __half2float(ll.x);
                    float r1 = __half2float(hh.y) + __half2float(ll.y);
                    float2 v = make_float2(v0 + bias[col] + r0, v1 + bias[col + 1] + r1);
                    *(float2*)(C + (size_t)r * Nn + col) = v;
                } else {
                    v0 += bias[col];
                    v1 += bias[col + 1];
                    v0 = 0.5f * v0 * (1.f + erff(v0 * 0.70710678118654752f));
                    v1 = 0.5f * v1 * (1.f + erff(v1 * 0.70710678118654752f));
                    __half2 hh; hh.x = __float2half(v0); hh.y = __float2half(v1);
                    *(__half2*)(Csplit + (size_t)r * nOut + col) = hh;
                }
            }
        }
    }
}

// ---------------- launcher ---------------------------------------------------
extern "C" void kernel_launch(void* const* d_in, const int* in_sizes, int n_in,
                              void* d_out, int out_size)
{
    const float* x   = (const float*)d_in[0];
    const float* src = (const float*)d_in[1];
    const float* c0w = (const float*)d_in[4];
    const float* c0b = (const float*)d_in[5];
    const float* c1w = (const float*)d_in[6];
    const float* c1b = (const float*)d_in[7];
    const float* n1g = (const float*)d_in[8];
    const float* n1b = (const float*)d_in[9];
    const float* qw  = (const float*)d_in[10];
    const float* kvw = (const float*)d_in[11];
    const float* pw  = (const float*)d_in[12];
    const float* pb  = (const float*)d_in[13];
    const float* n2g = (const float*)d_in[14];
    const float* n2b = (const float*)d_in[15];
    const float* f1w = (const float*)d_in[16];
    const float* f1b = (const float*)d_in[17];
    const float* f2w = (const float*)d_in[18];
    const float* f2b = (const float*)d_in[19];
    float* out = (float*)d_out;

    float *kvF, *attnP, *attn, *weff, *w2F, *x2F, *x3F;
    __half *xnS, *snS, *w2T, *kvwT, *f1wT, *f2wT, *ln2S, *h1S;
    cudaGetSymbolAddress((void**)&xnS, g_xnS);
    cudaGetSymbolAddress((void**)&snS, g_snS);
    cudaGetSymbolAddress((void**)&kvF, g_kvF);
    cudaGetSymbolAddress((void**)&attnP, g_attnP);
    cudaGetSymbolAddress((void**)&attn, g_attn);
    cudaGetSymbolAddress((void**)&weff, g_weff);
    cudaGetSymbolAddress((void**)&w2F, g_w2F);
    cudaGetSymbolAddress((void**)&w2T, g_w2T);
    cudaGetSymbolAddress((void**)&kvwT, g_kvwT);
    cudaGetSymbolAddress((void**)&f1wT, g_f1wT);
    cudaGetSymbolAddress((void**)&f2wT, g_f2wT);
    cudaGetSymbolAddress((void**)&x2F, g_x2F);
    cudaGetSymbolAddress((void**)&x3F, g_x3F);
    cudaGetSymbolAddress((void**)&ln2S, g_ln2S);
    cudaGetSymbolAddress((void**)&h1S, g_h1S);

    cudaFuncSetAttribute(gemm_mma<0>, cudaFuncAttributeMaxDynamicSharedMemorySize, MM_SMEM);
    cudaFuncSetAttribute(gemm_mma<1>, cudaFuncAttributeMaxDynamicSharedMemorySize, MM_SMEM);
    cudaFuncSetAttribute(gemm_mma<2>, cudaFuncAttributeMaxDynamicSharedMemorySize, MM_SMEM);
    cudaFuncSetAttribute(gemm_mma<3>, cudaFuncAttributeMaxDynamicSharedMemorySize, MM_SMEM);

    dim3 tb(32, 8);

    // idx 0: cpe0 + LN1 on x AND source
    cpe_ln_dual_kernel<<<dim3(BN / 4, 2), 128>>>(x, src, c0w, c0b, n1g, n1b, xnS, snS);
    // idx 1: kv weight transpose (fp16)
    splitT_kernel<<<dim3(2 * CC / 32, CC / 32), tb>>>(kvw, kvwT, CC, 2 * CC, 0, 0);
    // idx 2: fc1 weight transpose
    splitT_kernel<<<dim3(CHID / 32, CC / 32), tb>>>(f1w, f1wT, CC, CHID, 0, 0);
    // idx 3 (ncu capture target): kv = sn @ kv_w   (K = 384)
    gemm_mma<0><<<dim3(2 * CC / 128, BN / 128), 128, MM_SMEM>>>(
        snS, kvwT, nullptr, nullptr, nullptr, kvF, nullptr, 2 * CC, CC, CC, 0, 0);
    // idx 4: logits partials (atomic-free)
    logits_kernel<<<dim3(BB * NH, LSPLIT), 256>>>(kvF, attnP);
    // idx 5: reduce + softmax
    softmax_kernel<<<BB * NH, DD>>>(attnP, attn);
    // idx 6: fc2 weight transpose
    splitT_kernel<<<dim3(CC / 32, CHID / 32), tb>>>(f2w, f2wT, CHID, CC, 0, 0);

    // fold attn into proj_w, then q_w: W2[b] = q_w @ weff[b]
    weff_kernel<<<BB * NH, 256>>>(attn, pw, weff);
    gemm_f32s<<<dim3(CC / 64, CC / 64, BB), 256>>>(
        qw, weff, w2F, CC, CC, CC, (long long)CC * CC, (long long)CC * CC);
    splitT_kernel<<<dim3(CC / 32, CC / 32, BB), tb>>>(
        w2F, w2T, CC, CC, (long long)CC * CC, (long long)CC * CC);

    // x2 = xn @ W2[b] + proj_b + (xn residual from [hi|lo])   (K = 384, A stride 768)
    gemm_mma<3><<<dim3(CC / 128, BN / 128), 128, MM_SMEM>>>(
        xnS, w2T, pb, nullptr, xnS, x2F, nullptr, CC, CC, A1, 0, (long long)CC * CC);

    // cpe1 + LN2 (raw -> x3F, fp16 hi -> ln2S)
    cpe_ln_kernel<<<BN / 4, 128>>>(x2F, c1w, c1b, n2g, n2b, x3F, ln2S);

    // h1 = gelu(ln2 @ fc1_w + fc1_b)   (fp16 hi out)
    gemm_mma<2><<<dim3(CHID / 128, BN / 128), 128, MM_SMEM>>>(
        ln2S, f1wT, f1b, nullptr, nullptr, nullptr, h1S, CHID, CC, CC, CHID, 0);

    // out = h1 @ fc2_w + fc2_b + x3   (K = 1536)
    gemm_mma<1><<<dim3(CC / 128, BN / 128), 128, MM_SMEM>>>(
        h1S, f2wT, f2b, x3F, nullptr, out, nullptr, CC, CHID, CHID, 0, 0);
}